// round 13
// baseline (speedup 1.0000x reference)
#include <cuda_runtime.h>
#include <cuda_bf16.h>
#include <cstdint>

typedef __nv_bfloat16 bf16;

// ---------------- scratch (device globals; allocation is forbidden) --------
__device__ bf16 g_xh[8192 * 1024], g_xl[8192 * 1024];
__device__ bf16 g_w1h[3072 * 1024], g_w1l[3072 * 1024];  // Wq split
__device__ bf16 g_w2h[3072 * 1024], g_w2l[3072 * 1024];  // Wk split
__device__ bf16 g_w3h[3072 * 1024], g_w3l[3072 * 1024];  // Wo split
__device__ bf16 g_w4h[3072 * 1024], g_w4l[3072 * 1024];  // Wv split
__device__ float g_part[16 * 1024 * 1024];               // split-K partials (M:0-7, N:8-15)
__device__ float g_tp[24576];                            // tvec partials
__device__ float g_dp[24576];                            // dvec partials
__device__ bf16 g_mh[1024 * 1024], g_ml[1024 * 1024];    // M = Wq^T Wk
__device__ bf16 g_nh[1024 * 1024], g_nl[1024 * 1024];    // N = Wo Wv
__device__ bf16 g_xmh[8192 * 1024], g_xml[8192 * 1024];  // X*M
__device__ float g_s[8192 * 2048];                       // scores
__device__ bf16 g_ph[8192 * 2048], g_pl[8192 * 2048];    // probs
__device__ bf16 g_c2h[8192 * 1024], g_c2l[8192 * 1024];  // P*X
__device__ float g_tvec[1024];   // Wk^T bq
__device__ float g_bvec[8192];   // X * tvec
__device__ float g_dvec[1024];   // Wo bv + bo

// ---------------- events (static init; before harness mem checkpoints) ----
static cudaEvent_t g_ev[5];
namespace {
struct EvInit {
    EvInit() {
        for (int i = 0; i < 5; ++i)
            cudaEventCreateWithFlags(&g_ev[i], cudaEventDisableTiming);
    }
};
EvInit g_evinit;
}

// ---------------- helpers ---------------------------------------------------
__device__ __forceinline__ uint32_t smem_u32(const void* p) {
    uint32_t a;
    asm("{ .reg .u64 t; cvta.to.shared.u64 t, %1; cvt.u32.u64 %0, t; }"
        : "=r"(a) : "l"(p));
    return a;
}
__device__ __forceinline__ void cp16(uint32_t s, const void* g) {
    asm volatile("cp.async.cg.shared.global [%0], [%1], 16;" :: "r"(s), "l"(g));
}
__device__ __forceinline__ void cp_commit() {
    asm volatile("cp.async.commit_group;" ::: "memory");
}
__device__ __forceinline__ void cp_wait1() {
    asm volatile("cp.async.wait_group 1;" ::: "memory");
}
__device__ __forceinline__ void ldsm4(uint32_t* r, uint32_t a) {
    asm volatile("ldmatrix.sync.aligned.m8n8.x4.shared.b16 {%0,%1,%2,%3}, [%4];"
                 : "=r"(r[0]), "=r"(r[1]), "=r"(r[2]), "=r"(r[3]) : "r"(a));
}
__device__ __forceinline__ void ldsm4t(uint32_t* r, uint32_t a) {
    asm volatile("ldmatrix.sync.aligned.m8n8.x4.trans.shared.b16 {%0,%1,%2,%3}, [%4];"
                 : "=r"(r[0]), "=r"(r[1]), "=r"(r[2]), "=r"(r[3]) : "r"(a));
}
__device__ __forceinline__ void mma16816(float* d, const uint32_t* a, const uint32_t* b) {
    asm volatile("mma.sync.aligned.m16n8k16.row.col.f32.bf16.bf16.f32 "
                 "{%0,%1,%2,%3}, {%4,%5,%6,%7}, {%8,%9}, {%0,%1,%2,%3};"
                 : "+f"(d[0]), "+f"(d[1]), "+f"(d[2]), "+f"(d[3])
                 : "r"(a[0]), "r"(a[1]), "r"(a[2]), "r"(a[3]), "r"(b[0]), "r"(b[1]));
}
__device__ __forceinline__ void split2(float x, bf16& h, bf16& l) {
    h = __float2bfloat16(x);
    l = __float2bfloat16(x - __bfloat162float(h));
}
// FMA-pipe exp. rel err ~3.5e-7
__device__ __forceinline__ float fexp(float x) {
    x = fmaxf(x, -87.0f);
    const float t = x * 1.442695041f;
    const float i = rintf(t);
    const float f = t - i;
    float p = 1.54035e-4f;
    p = fmaf(p, f, 1.333356e-3f);
    p = fmaf(p, f, 9.618129e-3f);
    p = fmaf(p, f, 5.550410e-2f);
    p = fmaf(p, f, 2.402265e-1f);
    p = fmaf(p, f, 6.931472e-1f);
    p = fmaf(p, f, 1.0f);
    return __int_as_float(__float_as_int(p) + ((int)i << 23));
}

// ---------------------------------------------------------------------------
// D[m][n] = alpha * sum_k A[m][k] * B^T[n][k]  (+ bias[n])   (R11 core)
// ---------------------------------------------------------------------------
#define STG_B 32768
#define NSTG  3
#define SMEM_DYN (NSTG * STG_B)

template <bool TRA, bool TRB, int MODE, bool HOIST>
__device__ __forceinline__ void gemm_body(
    const bf16* __restrict__ Ah, const bf16* __restrict__ Al, int ldA,
    const bf16* __restrict__ Bh, const bf16* __restrict__ Bl, int ldB,
    float* __restrict__ Cf, bf16* __restrict__ Ch, bf16* __restrict__ Cl,
    int ldC, const float* __restrict__ bias, float alpha, int K, char* smem)
{
    __shared__ float bias_s[128];
    const uint32_t sb = smem_u32(smem);
    const int tid = threadIdx.x, lane = tid & 31, wid = tid >> 5;
    const int m0 = blockIdx.y * 128, n0 = blockIdx.x * 128;

    if (tid < 128) bias_s[tid] = bias ? bias[n0 + tid] : 0.0f;

    const size_t ldAs = (size_t)ldA, ldBs = (size_t)ldB;

    const int arow = tid >> 2, ac16 = tid & 3;
    const int krowL = tid >> 4, kc16 = tid & 15;
    const bf16 *pAh, *pAl;
    uint32_t sAoff;
    if constexpr (!TRA) {
        pAh = Ah + (size_t)(m0 + arow) * ldAs + ac16 * 8;
        pAl = Al + (size_t)(m0 + arow) * ldAs + ac16 * 8;
        sAoff = (uint32_t)arow * 64u + (uint32_t)((ac16 ^ ((arow >> 1) & 3)) << 4);
    } else {
        pAh = Ah + (size_t)krowL * ldAs + m0 + kc16 * 8;
        pAl = Al + (size_t)krowL * ldAs + m0 + kc16 * 8;
        sAoff = (uint32_t)krowL * 256u + (uint32_t)((kc16 ^ (krowL & 7)) << 4);
    }
    const bf16 *pBh, *pBl;
    uint32_t sBoff;
    if constexpr (!TRB) {
        pBh = Bh + (size_t)(n0 + arow) * ldBs + ac16 * 8;
        pBl = Bl + (size_t)(n0 + arow) * ldBs + ac16 * 8;
        sBoff = (uint32_t)arow * 64u + (uint32_t)((ac16 ^ ((arow >> 1) & 3)) << 4);
    } else {
        pBh = Bh + (size_t)krowL * ldBs + n0 + kc16 * 8;
        pBl = Bl + (size_t)krowL * ldBs + n0 + kc16 * 8;
        sBoff = (uint32_t)krowL * 256u + (uint32_t)((kc16 ^ (krowL & 7)) << 4);
    }

    auto load_stage = [&](int slot, int kt) {
        const uint32_t s0 = sb + (uint32_t)slot * STG_B;
        const size_t k0 = (size_t)kt * 32;
#pragma unroll
        for (int i = 0; i < 2; ++i) {
            if constexpr (!TRA) {
                cp16(s0 + i * 4096u + sAoff,         pAh + k0 + (size_t)(i * 64) * ldAs);
                cp16(s0 + 8192u + i * 4096u + sAoff, pAl + k0 + (size_t)(i * 64) * ldAs);
            } else {
                cp16(s0 + i * 4096u + sAoff,         pAh + (k0 + i * 16) * ldAs);
                cp16(s0 + 8192u + i * 4096u + sAoff, pAl + (k0 + i * 16) * ldAs);
            }
        }
#pragma unroll
        for (int i = 0; i < 2; ++i) {
            if constexpr (!TRB) {
                cp16(s0 + 16384u + i * 4096u + sBoff, pBh + k0 + (size_t)(i * 64) * ldBs);
                cp16(s0 + 24576u + i * 4096u + sBoff, pBl + k0 + (size_t)(i * 64) * ldBs);
            } else {
                cp16(s0 + 16384u + i * 4096u + sBoff, pBh + (k0 + i * 16) * ldBs);
                cp16(s0 + 24576u + i * 4096u + sBoff, pBl + (k0 + i * 16) * ldBs);
            }
        }
    };

    const int wm = (wid & 3) * 32, wn = (wid >> 2) * 64;
    const int rowAf = wm + (lane & 15);
    const uint32_t swzA = (uint32_t)((rowAf >> 1) & 3);
    const int nrow = wn + (lane & 7) + 8 * (lane >> 4);
    const uint32_t swzB = (uint32_t)((nrow >> 1) & 3);

    float C[2][8][4];
#pragma unroll
    for (int a = 0; a < 2; ++a)
#pragma unroll
        for (int b = 0; b < 8; ++b)
#pragma unroll
            for (int c = 0; c < 4; ++c) C[a][b][c] = 0.0f;

    const int nk = K >> 5;
    load_stage(0, 0); cp_commit();
    load_stage(1, 1); cp_commit();

    for (int kt = 0; kt < nk; ++kt) {
        cp_wait1();
        __syncthreads();
        if (kt + 2 < nk) load_stage((kt + 2) % NSTG, kt + 2);
        cp_commit();

        const uint32_t s0 = sb + (uint32_t)(kt % NSTG) * STG_B;
#pragma unroll
        for (int ks = 0; ks < 2; ++ks) {
            uint32_t aH[2][4], aL[2][4];
            if constexpr (!TRA) {
                const uint32_t kcA = (uint32_t)(ks * 2 + (lane >> 4));
#pragma unroll
                for (int mf = 0; mf < 2; ++mf) {
                    const uint32_t off = (uint32_t)(rowAf + 16 * mf) * 64u + ((kcA ^ swzA) << 4);
                    ldsm4(aH[mf], s0 + off);
                    ldsm4(aL[mf], s0 + 8192u + off);
                }
            } else {
                const uint32_t krow = (uint32_t)(ks * 16 + 8 * (lane >> 4) + (lane & 7));
                const uint32_t rowo = krow * 256u;
#pragma unroll
                for (int mf = 0; mf < 2; ++mf) {
                    const uint32_t c16 = (uint32_t)((wm >> 3) + 2 * mf + ((lane >> 3) & 1));
                    const uint32_t off = rowo + ((c16 ^ (uint32_t)(lane & 7)) << 4);
                    ldsm4t(aH[mf], s0 + off);
                    ldsm4t(aL[mf], s0 + 8192u + off);
                }
            }

#pragma unroll
            for (int nh = 0; nh < 2; ++nh) {
                if constexpr (HOIST) {
                    uint32_t bbh[2][4], bbl[2][4];
                    if constexpr (!TRB) {
                        const uint32_t kcB = (uint32_t)(ks * 2 + ((lane >> 3) & 1));
#pragma unroll
                        for (int j = 0; j < 2; ++j) {
                            const int nf2 = nh * 2 + j;
                            const uint32_t roff = (uint32_t)(nrow + 16 * nf2) * 64u +
                                                  ((kcB ^ swzB) << 4);
                            ldsm4(bbh[j], s0 + 16384u + roff);
                            ldsm4(bbl[j], s0 + 24576u + roff);
                        }
                    } else {
                        const uint32_t krow = (uint32_t)(ks * 16 + 8 * ((lane >> 3) & 1) + (lane & 7));
                        const uint32_t rowo = krow * 256u;
#pragma unroll
                        for (int j = 0; j < 2; ++j) {
                            const uint32_t c16 = (uint32_t)((wn >> 3) + (lane >> 4) + (nh * 2 + j) * 2);
                            const uint32_t coff = ((c16 ^ (uint32_t)(lane & 7)) << 4);
                            ldsm4t(bbh[j], s0 + 16384u + rowo + coff);
                            ldsm4t(bbl[j], s0 + 24576u + rowo + coff);
                        }
                    }
#pragma unroll
                    for (int mf = 0; mf < 2; ++mf)
#pragma unroll
                        for (int j = 0; j < 2; ++j) {
                            mma16816(C[mf][nh * 4 + j * 2 + 0], aH[mf], &bbh[j][0]);
                            mma16816(C[mf][nh * 4 + j * 2 + 1], aH[mf], &bbh[j][2]);
                        }
#pragma unroll
                    for (int mf = 0; mf < 2; ++mf)
#pragma unroll
                        for (int j = 0; j < 2; ++j) {
                            mma16816(C[mf][nh * 4 + j * 2 + 0], aL[mf], &bbh[j][0]);
                            mma16816(C[mf][nh * 4 + j * 2 + 1], aL[mf], &bbh[j][2]);
                        }
#pragma unroll
                    for (int mf = 0; mf < 2; ++mf)
#pragma unroll
                        for (int j = 0; j < 2; ++j) {
                            mma16816(C[mf][nh * 4 + j * 2 + 0], aH[mf], &bbl[j][0]);
                            mma16816(C[mf][nh * 4 + j * 2 + 1], aH[mf], &bbl[j][2]);
                        }
                } else {
                    uint32_t bb[2][4];
                    if constexpr (!TRB) {
                        const uint32_t kcB = (uint32_t)(ks * 2 + ((lane >> 3) & 1));
#pragma unroll
                        for (int j = 0; j < 2; ++j) {
                            const int nf2 = nh * 2 + j;
                            const uint32_t off = 16384u + (uint32_t)(nrow + 16 * nf2) * 64u +
                                                 ((kcB ^ swzB) << 4);
                            ldsm4(bb[j], s0 + off);
                        }
                    } else {
                        const uint32_t krow = (uint32_t)(ks * 16 + 8 * ((lane >> 3) & 1) + (lane & 7));
                        const uint32_t rowo = 16384u + krow * 256u;
#pragma unroll
                        for (int j = 0; j < 2; ++j) {
                            const uint32_t c16 = (uint32_t)((wn >> 3) + (lane >> 4) + (nh * 2 + j) * 2);
                            ldsm4t(bb[j], s0 + rowo + ((c16 ^ (uint32_t)(lane & 7)) << 4));
                        }
                    }
#pragma unroll
                    for (int mf = 0; mf < 2; ++mf)
#pragma unroll
                        for (int j = 0; j < 2; ++j) {
                            mma16816(C[mf][nh * 4 + j * 2 + 0], aH[mf], &bb[j][0]);
                            mma16816(C[mf][nh * 4 + j * 2 + 1], aH[mf], &bb[j][2]);
                        }
#pragma unroll
                    for (int mf = 0; mf < 2; ++mf)
#pragma unroll
                        for (int j = 0; j < 2; ++j) {
                            mma16816(C[mf][nh * 4 + j * 2 + 0], aL[mf], &bb[j][0]);
                            mma16816(C[mf][nh * 4 + j * 2 + 1], aL[mf], &bb[j][2]);
                        }
                    if constexpr (!TRB) {
                        const uint32_t kcB = (uint32_t)(ks * 2 + ((lane >> 3) & 1));
#pragma unroll
                        for (int j = 0; j < 2; ++j) {
                            const int nf2 = nh * 2 + j;
                            const uint32_t off = 24576u + (uint32_t)(nrow + 16 * nf2) * 64u +
                                                 ((kcB ^ swzB) << 4);
                            ldsm4(bb[j], s0 + off);
                        }
                    } else {
                        const uint32_t krow = (uint32_t)(ks * 16 + 8 * ((lane >> 3) & 1) + (lane & 7));
                        const uint32_t rowo = 24576u + krow * 256u;
#pragma unroll
                        for (int j = 0; j < 2; ++j) {
                            const uint32_t c16 = (uint32_t)((wn >> 3) + (lane >> 4) + (nh * 2 + j) * 2);
                            ldsm4t(bb[j], s0 + rowo + ((c16 ^ (uint32_t)(lane & 7)) << 4));
                        }
                    }
#pragma unroll
                    for (int mf = 0; mf < 2; ++mf)
#pragma unroll
                        for (int j = 0; j < 2; ++j) {
                            mma16816(C[mf][nh * 4 + j * 2 + 0], aH[mf], &bb[j][0]);
                            mma16816(C[mf][nh * 4 + j * 2 + 1], aH[mf], &bb[j][2]);
                        }
                }
            }
        }
    }

    const int mb = m0 + wm + (lane >> 2);
    const int nbl = wn + 2 * (lane & 3);
#pragma unroll
    for (int mf = 0; mf < 2; ++mf) {
        const size_t r0 = (size_t)(mb + 16 * mf);
#pragma unroll
        for (int nf = 0; nf < 8; ++nf) {
            const int cloc = nbl + nf * 8;
            const int c = n0 + cloc;
            const float b0 = bias_s[cloc], b1 = bias_s[cloc + 1];
            const float v0 = C[mf][nf][0] * alpha + b0;
            const float v1 = C[mf][nf][1] * alpha + b1;
            const float v2 = C[mf][nf][2] * alpha + b0;
            const float v3 = C[mf][nf][3] * alpha + b1;
            if constexpr (MODE == 0) {
                *(float2*)&Cf[r0 * ldC + c]       = make_float2(v0, v1);
                *(float2*)&Cf[(r0 + 8) * ldC + c] = make_float2(v2, v3);
            } else {
                bf16 h0, l0, h1, l1, h2, l2, h3, l3;
                split2(v0, h0, l0); split2(v1, h1, l1);
                split2(v2, h2, l2); split2(v3, h3, l3);
                *(__nv_bfloat162*)&Ch[r0 * ldC + c]       = __nv_bfloat162(h0, h1);
                *(__nv_bfloat162*)&Cl[r0 * ldC + c]       = __nv_bfloat162(l0, l1);
                *(__nv_bfloat162*)&Ch[(r0 + 8) * ldC + c] = __nv_bfloat162(h2, h3);
                *(__nv_bfloat162*)&Cl[(r0 + 8) * ldC + c] = __nv_bfloat162(l2, l3);
            }
        }
    }
}

template <bool TRA, bool TRB, int MODE>
__global__ void __launch_bounds__(256, 2)
mma_gemm(const bf16* __restrict__ Ah, const bf16* __restrict__ Al, int ldA, long long sAz,
         const bf16* __restrict__ Bh, const bf16* __restrict__ Bl, int ldB, long long sBz,
         float* __restrict__ Cf, bf16* __restrict__ Ch, bf16* __restrict__ Cl,
         int ldC, long long sCz, const float* __restrict__ bias, float alpha, int K)
{
    extern __shared__ char smem[];
    const long long z = blockIdx.z;
    gemm_body<TRA, TRB, MODE, false>(
        Ah + z * sAz, Al + z * sAz, ldA, Bh + z * sBz, Bl + z * sBz, ldB,
        (MODE == 0) ? Cf + z * sCz : Cf,
        (MODE == 1) ? Ch + z * sCz : Ch,
        (MODE == 1) ? Cl + z * sCz : Cl,
        ldC, bias, alpha, K, smem);
}

// ---- M = Wq^T Wk, split-K=8 (z 0-7), slabs part[0..8M) ---------------------
__global__ void __launch_bounds__(256, 2)
mnM_gemm(const bf16* __restrict__ w1h, const bf16* __restrict__ w1l,
         const bf16* __restrict__ w2h, const bf16* __restrict__ w2l,
         float* __restrict__ part)
{
    extern __shared__ char smem[];
    const int z = blockIdx.z;
    float* Cf = part + (size_t)z * 1048576;
    const size_t o = (size_t)z * 384 * 1024;
    gemm_body<true, true, 0, true>(w1h + o, w1l + o, 1024, w2h + o, w2l + o, 1024,
                                   Cf, nullptr, nullptr, 1024, nullptr, 1.0f, 384, smem);
}

// ---- N = Wo Wv, split-K=8 (z 0-7), slabs part[8M..16M) ---------------------
__global__ void __launch_bounds__(256, 2)
mnN_gemm(const bf16* __restrict__ w3h, const bf16* __restrict__ w3l,
         const bf16* __restrict__ w4h, const bf16* __restrict__ w4l,
         float* __restrict__ part)
{
    extern __shared__ char smem[];
    const int z = blockIdx.z;
    float* Cf = part + 8388608 + (size_t)z * 1048576;
    const size_t oB = (size_t)z * 384 * 1024;
    gemm_body<false, true, 0, true>(w3h + z * 384, w3l + z * 384, 3072,
                                    w4h + oB, w4l + oB, 1024,
                                    Cf, nullptr, nullptr, 1024, nullptr, 1.0f, 384, smem);
}

// ---------------------------------------------------------------------------
// prepQK: Wq/Wk splits + tvec partials.  blocks: Wq [0,3072) | Wk [3072,6144)
//         | tvec [6144,6336)
// ---------------------------------------------------------------------------
__global__ void __launch_bounds__(256)
prepQK_kernel(const float* __restrict__ Wq, const float* __restrict__ Wk,
              const float* __restrict__ bq,
              bf16* __restrict__ w1h, bf16* __restrict__ w1l,
              bf16* __restrict__ w2h, bf16* __restrict__ w2l,
              float* __restrict__ tpart)
{
    __shared__ float sred[256];
    const int b = blockIdx.x;
    const int tid = threadIdx.x;

    if (b < 6144) {
        const float* src; bf16 *dh, *dl; int i0;
        if (b < 3072) { src = Wq; dh = w1h; dl = w1l; i0 = b; }
        else          { src = Wk; dh = w2h; dl = w2l; i0 = b - 3072; }
        const int i = i0 * 256 + tid;
        const float4 v = ((const float4*)src)[i];
        bf16 h0, h1, h2, h3, l0, l1, l2, l3;
        split2(v.x, h0, l0); split2(v.y, h1, l1);
        split2(v.z, h2, l2); split2(v.w, h3, l3);
        ((__nv_bfloat162*)dh)[2 * i]     = __nv_bfloat162(h0, h1);
        ((__nv_bfloat162*)dh)[2 * i + 1] = __nv_bfloat162(h2, h3);
        ((__nv_bfloat162*)dl)[2 * i]     = __nv_bfloat162(l0, l1);
        ((__nv_bfloat162*)dl)[2 * i + 1] = __nv_bfloat162(l2, l3);
    } else {
        const int t = b - 6144;           // 0..191
        const int ec = t / 8, dc = t % 8;
        const int d = dc * 128 + (tid & 127);
        const int el = tid >> 7;
        float acc = 0.0f;
#pragma unroll 8
        for (int j = 0; j < 64; ++j) {
            const int e = ec * 128 + el * 64 + j;
            acc += Wk[(size_t)e * 1024 + d] * bq[e];
        }
        sred[tid] = acc;
        __syncthreads();
        if (tid < 128) tpart[ec * 1024 + d] = sred[tid] + sred[tid + 128];
    }
}

// ---------------------------------------------------------------------------
// prepOV: Wo/Wv splits + dvec partials.  blocks: Wo [0,3072) | Wv [3072,6144)
//         | dvec [6144,9216)
// ---------------------------------------------------------------------------
__global__ void __launch_bounds__(256)
prepOV_kernel(const float* __restrict__ Wo, const float* __restrict__ Wv,
              const float* __restrict__ bv,
              bf16* __restrict__ w3h, bf16* __restrict__ w3l,
              bf16* __restrict__ w4h, bf16* __restrict__ w4l,
              float* __restrict__ dpart)
{
    const int b = blockIdx.x;
    const int tid = threadIdx.x;

    if (b < 6144) {
        const float* src; bf16 *dh, *dl; int i0;
        if (b < 3072) { src = Wo; dh = w3h; dl = w3l; i0 = b; }
        else          { src = Wv; dh = w4h; dl = w4l; i0 = b - 3072; }
        const int i = i0 * 256 + tid;
        const float4 v = ((const float4*)src)[i];
        bf16 h0, h1, h2, h3, l0, l1, l2, l3;
        split2(v.x, h0, l0); split2(v.y, h1, l1);
        split2(v.z, h2, l2); split2(v.w, h3, l3);
        ((__nv_bfloat162*)dh)[2 * i]     = __nv_bfloat162(h0, h1);
        ((__nv_bfloat162*)dh)[2 * i + 1] = __nv_bfloat162(h2, h3);
        ((__nv_bfloat162*)dl)[2 * i]     = __nv_bfloat162(l0, l1);
        ((__nv_bfloat162*)dl)[2 * i + 1] = __nv_bfloat162(l2, l3);
    } else {
        const int fw = (b - 6144) * 8 + (tid >> 5);  // flat warp 0..24575
        const int row = fw / 24, ch = fw % 24;
        const int lane = tid & 31;
        const float4 a = *(const float4*)&Wo[(size_t)row * 3072 + ch * 128 + lane * 4];
        const float4 c = *(const float4*)&bv[ch * 128 + lane * 4];
        float acc = a.x * c.x + a.y * c.y + a.z * c.z + a.w * c.w;
#pragma unroll
        for (int o = 16; o > 0; o >>= 1) acc += __shfl_xor_sync(0xffffffffu, acc, o);
        if (lane == 0) dpart[ch * 1024 + row] = acc;
    }
}

// ---------------- prepX: X split only ---------------------------------------
__global__ void __launch_bounds__(256)
prepX_kernel(const float* __restrict__ x, bf16* __restrict__ xh, bf16* __restrict__ xl)
{
    const int i = blockIdx.x * 256 + threadIdx.x;
    const float4 v = ((const float4*)x)[i];
    bf16 h0, h1, h2, h3, l0, l1, l2, l3;
    split2(v.x, h0, l0); split2(v.y, h1, l1);
    split2(v.z, h2, l2); split2(v.w, h3, l3);
    ((__nv_bfloat162*)xh)[2 * i]     = __nv_bfloat162(h0, h1);
    ((__nv_bfloat162*)xh)[2 * i + 1] = __nv_bfloat162(h2, h3);
    ((__nv_bfloat162*)xl)[2 * i]     = __nv_bfloat162(l0, l1);
    ((__nv_bfloat162*)xl)[2 * i + 1] = __nv_bfloat162(l2, l3);
}

__global__ void __launch_bounds__(256)
vec_reduce(const float* __restrict__ tpart, const float* __restrict__ dpart,
           const float* __restrict__ bo, float* __restrict__ t, float* __restrict__ dv)
{
    const int i = blockIdx.x * 256 + threadIdx.x;
    if (i < 1024) {
        float a = 0.0f;
#pragma unroll
        for (int e = 0; e < 24; ++e) a += tpart[e * 1024 + i];
        t[i] = a;
    } else {
        const int j = i - 1024;
        float a = 0.0f;
#pragma unroll
        for (int e = 0; e < 24; ++e) a += dpart[e * 1024 + j];
        dv[j] = a + bo[j];
    }
}

// ---- combine one matrix (8 slabs starting at `base`) -> hi/lo split --------
__global__ void __launch_bounds__(256)
combine1(const float* __restrict__ base, bf16* __restrict__ hi, bf16* __restrict__ lo)
{
    const int i = blockIdx.x * 256 + threadIdx.x;   // float4 idx, 262144 total
    float4 x = make_float4(0.f, 0.f, 0.f, 0.f);
#pragma unroll
    for (int s2 = 0; s2 < 8; ++s2) {
        const float4 a = ((const float4*)base)[i + s2 * 262144];
        x.x += a.x; x.y += a.y; x.z += a.z; x.w += a.w;
    }
    bf16 h0, h1, h2, h3, l0, l1, l2, l3;
    split2(x.x, h0, l0); split2(x.y, h1, l1);
    split2(x.z, h2, l2); split2(x.w, h3, l3);
    ((__nv_bfloat162*)hi)[2 * i]     = __nv_bfloat162(h0, h1);
    ((__nv_bfloat162*)hi)[2 * i + 1] = __nv_bfloat162(h2, h3);
    ((__nv_bfloat162*)lo)[2 * i]     = __nv_bfloat162(l0, l1);
    ((__nv_bfloat162*)lo)[2 * i + 1] = __nv_bfloat162(l2, l3);
}

__global__ void __launch_bounds__(256)
bvec_kernel(const float* __restrict__ X, const float* __restrict__ t,
            float* __restrict__ b)
{
    const int w = (blockIdx.x * 256 + threadIdx.x) >> 5;
    const int lane = threadIdx.x & 31;
    const float* row = X + (size_t)w * 1024;
    float acc = 0.0f;
#pragma unroll
    for (int j = 0; j < 8; ++j) {
        const float4 a = *(const float4*)&row[(lane + j * 32) * 4];
        const float4 c = *(const float4*)&t[(lane + j * 32) * 4];
        acc += a.x * c.x + a.y * c.y + a.z * c.z + a.w * c.w;
    }
#pragma unroll
    for (int o = 16; o > 0; o >>= 1) acc += __shfl_xor_sync(0xffffffffu, acc, o);
    if (lane == 0) b[w] = acc;
}

__global__ void __launch_bounds__(256)
softmax_split(const float* __restrict__ S, const float* __restrict__ bvec,
              bf16* __restrict__ ph, bf16* __restrict__ pl)
{
    const long long row = blockIdx.x;
    const float* p = S + row * 2048;
    const float* bv = bvec + ((row >> 11) << 11);
    const int t = threadIdx.x;

    float4 x0 = *(const float4*)&p[t * 4];
    float4 x1 = *(const float4*)&p[1024 + t * 4];
    const float4 c0 = *(const float4*)&bv[t * 4];
    const float4 c1 = *(const float4*)&bv[1024 + t * 4];
    x0.x += 0.125f * c0.x; x0.y += 0.125f * c0.y;
    x0.z += 0.125f * c0.z; x0.w += 0.125f * c0.w;
    x1.x += 0.125f * c1.x; x1.y += 0.125f * c1.y;
    x1.z += 0.125f * c1.z; x1.w += 0.125f * c1.w;

    float m = fmaxf(fmaxf(fmaxf(x0.x, x0.y), fmaxf(x0.z, x0.w)),
                    fmaxf(fmaxf(x1.x, x1.y), fmaxf(x1.z, x1.w)));
#pragma unroll
    for (int o = 16; o > 0; o >>= 1) m = fmaxf(m, __shfl_xor_sync(0xffffffffu, m, o));
    __shared__ float red[8];
    if ((t & 31) == 0) red[t >> 5] = m;
    __syncthreads();
    m = fmaxf(fmaxf(fmaxf(red[0], red[1]), fmaxf(red[2], red[3])),
              fmaxf(fmaxf(red[4], red[5]), fmaxf(red[6], red[7])));
    __syncthreads();

    float e[8];
    e[0] = fexp(x0.x - m); e[1] = fexp(x0.y - m);
    e[2] = fexp(x0.z - m); e[3] = fexp(x0.w - m);
    e[4] = fexp(x1.x - m); e[5] = fexp(x1.y - m);
    e[6] = fexp(x1.z - m); e[7] = fexp(x1.w - m);

    float s = ((e[0] + e[1]) + (e[2] + e[3])) + ((e[4] + e[5]) + (e[6] + e[7]));
#pragma unroll
    for (int o = 16; o > 0; o >>= 1) s += __shfl_xor_sync(0xffffffffu, s, o);
    if ((t & 31) == 0) red[t >> 5] = s;
    __syncthreads();
    const float inv = 1.0f / (((red[0] + red[1]) + (red[2] + red[3])) +
                              ((red[4] + red[5]) + (red[6] + red[7])));

    bf16* hp = ph + row * 2048;
    bf16* lp = pl + row * 2048;
#pragma unroll
    for (int g = 0; g < 2; ++g) {
        bf16 hh[4], ll[4];
#pragma unroll
        for (int j = 0; j < 4; ++j) split2(e[g * 4 + j] * inv, hh[j], ll[j]);
        const int base = g * 1024 + t * 4;
        *(__nv_bfloat162*)&hp[base]     = __nv_bfloat162(hh[0], hh[1]);
        *(__nv_bfloat162*)&hp[base + 2] = __nv_bfloat162(hh[2], hh[3]);
        *(__nv_bfloat162*)&lp[base]     = __nv_bfloat162(ll[0], ll[1]);
        *(__nv_bfloat162*)&lp[base + 2] = __nv_bfloat162(ll[2], ll[3]);
    }
}

// ---------------------------------------------------------------------------
extern "C" void kernel_launch(void* const* d_in, const int* in_sizes, int n_in,
                              void* d_out, int out_size)
{
    (void)in_sizes; (void)n_in; (void)out_size;
    const float* x  = (const float*)d_in[0];
    const float* Wq = (const float*)d_in[1];
    const float* bq = (const float*)d_in[2];
    const float* Wk = (const float*)d_in[3];
    const float* bk = (const float*)d_in[4];  (void)bk;  // cancels in softmax
    const float* Wv = (const float*)d_in[5];
    const float* bv = (const float*)d_in[6];
    const float* Wo = (const float*)d_in[7];
    const float* bo = (const float*)d_in[8];
    float* out = (float*)d_out;

    bf16 *xh, *xl, *w1h, *w1l, *w2h, *w2l, *w3h, *w3l, *w4h, *w4l;
    bf16 *mh, *ml, *nh, *nl, *xmh, *xml, *ph, *pl, *c2h, *c2l;
    float *part, *tp, *dp, *s, *tv, *bvv, *dv;
    cudaGetSymbolAddress((void**)&xh, g_xh);   cudaGetSymbolAddress((void**)&xl, g_xl);
    cudaGetSymbolAddress((void**)&w1h, g_w1h); cudaGetSymbolAddress((void**)&w1l, g_w1l);
    cudaGetSymbolAddress((void**)&w2h, g_w2h); cudaGetSymbolAddress((void**)&w2l, g_w2l);
    cudaGetSymbolAddress((void**)&w3h, g_w3h); cudaGetSymbolAddress((void**)&w3l, g_w3l);
    cudaGetSymbolAddress((void**)&w4h, g_w4h); cudaGetSymbolAddress((void**)&w4l, g_w4l);
    cudaGetSymbolAddress((void**)&part, g_part);
    cudaGetSymbolAddress((void**)&tp, g_tp);   cudaGetSymbolAddress((void**)&dp, g_dp);
    cudaGetSymbolAddress((void**)&mh, g_mh);   cudaGetSymbolAddress((void**)&ml, g_ml);
    cudaGetSymbolAddress((void**)&nh, g_nh);   cudaGetSymbolAddress((void**)&nl, g_nl);
    cudaGetSymbolAddress((void**)&xmh, g_xmh); cudaGetSymbolAddress((void**)&xml, g_xml);
    cudaGetSymbolAddress((void**)&s, g_s);
    cudaGetSymbolAddress((void**)&ph, g_ph);   cudaGetSymbolAddress((void**)&pl, g_pl);
    cudaGetSymbolAddress((void**)&c2h, g_c2h); cudaGetSymbolAddress((void**)&c2l, g_c2l);
    cudaGetSymbolAddress((void**)&tv, g_tvec);
    cudaGetSymbolAddress((void**)&bvv, g_bvec);
    cudaGetSymbolAddress((void**)&dv, g_dvec);

    cudaFuncSetAttribute(mma_gemm<false, false, 0>, cudaFuncAttributeMaxDynamicSharedMemorySize, SMEM_DYN);
    cudaFuncSetAttribute(mma_gemm<false, true, 1>,  cudaFuncAttributeMaxDynamicSharedMemorySize, SMEM_DYN);
    cudaFuncSetAttribute(mnM_gemm,                  cudaFuncAttributeMaxDynamicSharedMemorySize, SMEM_DYN);
    cudaFuncSetAttribute(mnN_gemm,                  cudaFuncAttributeMaxDynamicSharedMemorySize, SMEM_DYN);

    const long long QS = 2048LL * 1024, SS = 2048LL * 2048;

    cudaStream_t s0 = 0;
    cudaStream_t sB = cudaStreamPerThread;
    cudaEvent_t evRoot = g_ev[0], evQK = g_ev[1], evM = g_ev[2],
                evCM = g_ev[3], evCN = g_ev[4];

    // ---- fork ---------------------------------------------------------------
    cudaEventRecord(evRoot, s0);
    cudaStreamWaitEvent(sB, evRoot, 0);

    // s0: critical path — Wq/Wk split, then M product immediately
    prepQK_kernel<<<6336, 256, 0, s0>>>(Wq, Wk, bq, w1h, w1l, w2h, w2l, tp);
    cudaEventRecord(evQK, s0);
    mnM_gemm<<<dim3(8, 8, 8), 256, SMEM_DYN, s0>>>(w1h, w1l, w2h, w2l, part);
    cudaEventRecord(evM, s0);

    // sB: everything else hides under mnM / XM / scores
    prepX_kernel<<<8192, 256, 0, sB>>>(x, xh, xl);
    prepOV_kernel<<<9216, 256, 0, sB>>>(Wo, Wv, bv, w3h, w3l, w4h, w4l, dp);
    cudaStreamWaitEvent(sB, evQK, 0);
    vec_reduce<<<8, 256, 0, sB>>>(tp, dp, bo, tv, dv);
    bvec_kernel<<<1024, 256, 0, sB>>>(x, tv, bvv);
    cudaStreamWaitEvent(sB, evM, 0);
    combine1<<<1024, 256, 0, sB>>>(part, mh, ml);
    cudaEventRecord(evCM, sB);
    mnN_gemm<<<dim3(8, 8, 8), 256, SMEM_DYN, sB>>>(w3h, w3l, w4h, w4l, part);
    combine1<<<1024, 256, 0, sB>>>(part + 8388608, nh, nl);
    cudaEventRecord(evCN, sB);

    // s0: main chain (waits M combine; prepX/bvec are ordered before evCM on sB)
    cudaStreamWaitEvent(s0, evCM, 0);

    // XM = X * M  (B = M row-major [k][n] -> TRB)
    mma_gemm<false, true, 1><<<dim3(8, 64, 1), 256, SMEM_DYN, s0>>>(
        xh, xl, 1024, 0, mh, ml, 1024, 0,
        nullptr, xmh, xml, 1024, 0, nullptr, 1.0f, 1024);

    // scores = 0.125 * (XM) X^T per batch
    mma_gemm<false, false, 0><<<dim3(16, 16, 4), 256, SMEM_DYN, s0>>>(
        xmh, xml, 1024, QS, xh, xl, 1024, QS,
        s, nullptr, nullptr, 2048, SS, nullptr, 0.125f, 1024);

    // softmax (adds 0.125*b_m) -> split probs
    softmax_split<<<8192, 256, 0, s0>>>(s, bvv, ph, pl);

    // C2 = P X per batch (B = X [k][n] -> TRB)
    mma_gemm<false, true, 1><<<dim3(8, 16, 4), 256, SMEM_DYN, s0>>>(
        ph, pl, 2048, SS, xh, xl, 1024, QS,
        nullptr, c2h, c2l, 1024, QS, nullptr, 1.0f, 2048);

    // out = C2 N^T + d (needs N)
    cudaStreamWaitEvent(s0, evCN, 0);
    mma_gemm<false, false, 0><<<dim3(8, 64, 1), 256, SMEM_DYN, s0>>>(
        c2h, c2l, 1024, 0, nh, nl, 1024, 0,
        out, nullptr, nullptr, 1024, 0, dv, 1.0f, 1024);
}

// round 14
// speedup vs baseline: 1.0168x; 1.0168x over previous
#include <cuda_runtime.h>
#include <cuda_bf16.h>
#include <cstdint>

typedef __nv_bfloat16 bf16;

// ---------------- scratch (device globals; allocation is forbidden) --------
__device__ bf16 g_xh[8192 * 1024], g_xl[8192 * 1024];
__device__ bf16 g_w1h[3072 * 1024], g_w1l[3072 * 1024];  // Wq split
__device__ bf16 g_w2h[3072 * 1024], g_w2l[3072 * 1024];  // Wk split
__device__ bf16 g_w3h[3072 * 1024], g_w3l[3072 * 1024];  // Wo split
__device__ bf16 g_w4h[3072 * 1024], g_w4l[3072 * 1024];  // Wv split
__device__ float g_part[16 * 1024 * 1024];               // split-K partials (M:0-7, N:8-15)
__device__ float g_tp[24576];                            // tvec partials
__device__ float g_dp[24576];                            // dvec partials
__device__ bf16 g_mh[1024 * 1024], g_ml[1024 * 1024];    // M = Wq^T Wk
__device__ bf16 g_nh[1024 * 1024], g_nl[1024 * 1024];    // N = Wo Wv
__device__ bf16 g_xmh[8192 * 1024], g_xml[8192 * 1024];  // X*M
__device__ float g_s[8192 * 2048];                       // scores
__device__ bf16 g_ph[8192 * 2048], g_pl[8192 * 2048];    // probs
__device__ bf16 g_c2h[8192 * 1024], g_c2l[8192 * 1024];  // P*X
__device__ float g_tvec[1024];   // Wk^T bq
__device__ float g_bvec[8192];   // X * tvec
__device__ float g_dvec[1024];   // Wo bv + bo

// ---------------- events (static init; before harness mem checkpoints) ----
static cudaEvent_t g_ev[6];
namespace {
struct EvInit {
    EvInit() {
        for (int i = 0; i < 6; ++i)
            cudaEventCreateWithFlags(&g_ev[i], cudaEventDisableTiming);
    }
};
EvInit g_evinit;
}

// ---------------- helpers ---------------------------------------------------
__device__ __forceinline__ uint32_t smem_u32(const void* p) {
    uint32_t a;
    asm("{ .reg .u64 t; cvta.to.shared.u64 t, %1; cvt.u32.u64 %0, t; }"
        : "=r"(a) : "l"(p));
    return a;
}
__device__ __forceinline__ void cp16(uint32_t s, const void* g) {
    asm volatile("cp.async.cg.shared.global [%0], [%1], 16;" :: "r"(s), "l"(g));
}
__device__ __forceinline__ void cp_commit() {
    asm volatile("cp.async.commit_group;" ::: "memory");
}
__device__ __forceinline__ void cp_wait1() {
    asm volatile("cp.async.wait_group 1;" ::: "memory");
}
__device__ __forceinline__ void ldsm4(uint32_t* r, uint32_t a) {
    asm volatile("ldmatrix.sync.aligned.m8n8.x4.shared.b16 {%0,%1,%2,%3}, [%4];"
                 : "=r"(r[0]), "=r"(r[1]), "=r"(r[2]), "=r"(r[3]) : "r"(a));
}
__device__ __forceinline__ void ldsm4t(uint32_t* r, uint32_t a) {
    asm volatile("ldmatrix.sync.aligned.m8n8.x4.trans.shared.b16 {%0,%1,%2,%3}, [%4];"
                 : "=r"(r[0]), "=r"(r[1]), "=r"(r[2]), "=r"(r[3]) : "r"(a));
}
__device__ __forceinline__ void mma16816(float* d, const uint32_t* a, const uint32_t* b) {
    asm volatile("mma.sync.aligned.m16n8k16.row.col.f32.bf16.bf16.f32 "
                 "{%0,%1,%2,%3}, {%4,%5,%6,%7}, {%8,%9}, {%0,%1,%2,%3};"
                 : "+f"(d[0]), "+f"(d[1]), "+f"(d[2]), "+f"(d[3])
                 : "r"(a[0]), "r"(a[1]), "r"(a[2]), "r"(a[3]), "r"(b[0]), "r"(b[1]));
}
__device__ __forceinline__ void split2(float x, bf16& h, bf16& l) {
    h = __float2bfloat16(x);
    l = __float2bfloat16(x - __bfloat162float(h));
}
// FMA-pipe exp. rel err ~3.5e-7
__device__ __forceinline__ float fexp(float x) {
    x = fmaxf(x, -87.0f);
    const float t = x * 1.442695041f;
    const float i = rintf(t);
    const float f = t - i;
    float p = 1.54035e-4f;
    p = fmaf(p, f, 1.333356e-3f);
    p = fmaf(p, f, 9.618129e-3f);
    p = fmaf(p, f, 5.550410e-2f);
    p = fmaf(p, f, 2.402265e-1f);
    p = fmaf(p, f, 6.931472e-1f);
    p = fmaf(p, f, 1.0f);
    return __int_as_float(__float_as_int(p) + ((int)i << 23));
}

// ---------------------------------------------------------------------------
// D[m][n] = alpha * sum_k A[m][k] * B^T[n][k]  (+ bias[n])   (R11 core)
// ---------------------------------------------------------------------------
#define STG_B 32768
#define NSTG  3
#define SMEM_DYN (NSTG * STG_B)

template <bool TRA, bool TRB, int MODE, bool HOIST>
__device__ __forceinline__ void gemm_body(
    const bf16* __restrict__ Ah, const bf16* __restrict__ Al, int ldA,
    const bf16* __restrict__ Bh, const bf16* __restrict__ Bl, int ldB,
    float* __restrict__ Cf, bf16* __restrict__ Ch, bf16* __restrict__ Cl,
    int ldC, const float* __restrict__ bias, float alpha, int K, char* smem)
{
    __shared__ float bias_s[128];
    const uint32_t sb = smem_u32(smem);
    const int tid = threadIdx.x, lane = tid & 31, wid = tid >> 5;
    const int m0 = blockIdx.y * 128, n0 = blockIdx.x * 128;

    if (tid < 128) bias_s[tid] = bias ? bias[n0 + tid] : 0.0f;

    const size_t ldAs = (size_t)ldA, ldBs = (size_t)ldB;

    const int arow = tid >> 2, ac16 = tid & 3;
    const int krowL = tid >> 4, kc16 = tid & 15;
    const bf16 *pAh, *pAl;
    uint32_t sAoff;
    if constexpr (!TRA) {
        pAh = Ah + (size_t)(m0 + arow) * ldAs + ac16 * 8;
        pAl = Al + (size_t)(m0 + arow) * ldAs + ac16 * 8;
        sAoff = (uint32_t)arow * 64u + (uint32_t)((ac16 ^ ((arow >> 1) & 3)) << 4);
    } else {
        pAh = Ah + (size_t)krowL * ldAs + m0 + kc16 * 8;
        pAl = Al + (size_t)krowL * ldAs + m0 + kc16 * 8;
        sAoff = (uint32_t)krowL * 256u + (uint32_t)((kc16 ^ (krowL & 7)) << 4);
    }
    const bf16 *pBh, *pBl;
    uint32_t sBoff;
    if constexpr (!TRB) {
        pBh = Bh + (size_t)(n0 + arow) * ldBs + ac16 * 8;
        pBl = Bl + (size_t)(n0 + arow) * ldBs + ac16 * 8;
        sBoff = (uint32_t)arow * 64u + (uint32_t)((ac16 ^ ((arow >> 1) & 3)) << 4);
    } else {
        pBh = Bh + (size_t)krowL * ldBs + n0 + kc16 * 8;
        pBl = Bl + (size_t)krowL * ldBs + n0 + kc16 * 8;
        sBoff = (uint32_t)krowL * 256u + (uint32_t)((kc16 ^ (krowL & 7)) << 4);
    }

    auto load_stage = [&](int slot, int kt) {
        const uint32_t s0 = sb + (uint32_t)slot * STG_B;
        const size_t k0 = (size_t)kt * 32;
#pragma unroll
        for (int i = 0; i < 2; ++i) {
            if constexpr (!TRA) {
                cp16(s0 + i * 4096u + sAoff,         pAh + k0 + (size_t)(i * 64) * ldAs);
                cp16(s0 + 8192u + i * 4096u + sAoff, pAl + k0 + (size_t)(i * 64) * ldAs);
            } else {
                cp16(s0 + i * 4096u + sAoff,         pAh + (k0 + i * 16) * ldAs);
                cp16(s0 + 8192u + i * 4096u + sAoff, pAl + (k0 + i * 16) * ldAs);
            }
        }
#pragma unroll
        for (int i = 0; i < 2; ++i) {
            if constexpr (!TRB) {
                cp16(s0 + 16384u + i * 4096u + sBoff, pBh + k0 + (size_t)(i * 64) * ldBs);
                cp16(s0 + 24576u + i * 4096u + sBoff, pBl + k0 + (size_t)(i * 64) * ldBs);
            } else {
                cp16(s0 + 16384u + i * 4096u + sBoff, pBh + (k0 + i * 16) * ldBs);
                cp16(s0 + 24576u + i * 4096u + sBoff, pBl + (k0 + i * 16) * ldBs);
            }
        }
    };

    const int wm = (wid & 3) * 32, wn = (wid >> 2) * 64;
    const int rowAf = wm + (lane & 15);
    const uint32_t swzA = (uint32_t)((rowAf >> 1) & 3);
    const int nrow = wn + (lane & 7) + 8 * (lane >> 4);
    const uint32_t swzB = (uint32_t)((nrow >> 1) & 3);

    float C[2][8][4];
#pragma unroll
    for (int a = 0; a < 2; ++a)
#pragma unroll
        for (int b = 0; b < 8; ++b)
#pragma unroll
            for (int c = 0; c < 4; ++c) C[a][b][c] = 0.0f;

    const int nk = K >> 5;
    load_stage(0, 0); cp_commit();
    load_stage(1, 1); cp_commit();

    for (int kt = 0; kt < nk; ++kt) {
        cp_wait1();
        __syncthreads();
        if (kt + 2 < nk) load_stage((kt + 2) % NSTG, kt + 2);
        cp_commit();

        const uint32_t s0 = sb + (uint32_t)(kt % NSTG) * STG_B;
#pragma unroll
        for (int ks = 0; ks < 2; ++ks) {
            uint32_t aH[2][4], aL[2][4];
            if constexpr (!TRA) {
                const uint32_t kcA = (uint32_t)(ks * 2 + (lane >> 4));
#pragma unroll
                for (int mf = 0; mf < 2; ++mf) {
                    const uint32_t off = (uint32_t)(rowAf + 16 * mf) * 64u + ((kcA ^ swzA) << 4);
                    ldsm4(aH[mf], s0 + off);
                    ldsm4(aL[mf], s0 + 8192u + off);
                }
            } else {
                const uint32_t krow = (uint32_t)(ks * 16 + 8 * (lane >> 4) + (lane & 7));
                const uint32_t rowo = krow * 256u;
#pragma unroll
                for (int mf = 0; mf < 2; ++mf) {
                    const uint32_t c16 = (uint32_t)((wm >> 3) + 2 * mf + ((lane >> 3) & 1));
                    const uint32_t off = rowo + ((c16 ^ (uint32_t)(lane & 7)) << 4);
                    ldsm4t(aH[mf], s0 + off);
                    ldsm4t(aL[mf], s0 + 8192u + off);
                }
            }

#pragma unroll
            for (int nh = 0; nh < 2; ++nh) {
                if constexpr (HOIST) {
                    uint32_t bbh[2][4], bbl[2][4];
                    if constexpr (!TRB) {
                        const uint32_t kcB = (uint32_t)(ks * 2 + ((lane >> 3) & 1));
#pragma unroll
                        for (int j = 0; j < 2; ++j) {
                            const int nf2 = nh * 2 + j;
                            const uint32_t roff = (uint32_t)(nrow + 16 * nf2) * 64u +
                                                  ((kcB ^ swzB) << 4);
                            ldsm4(bbh[j], s0 + 16384u + roff);
                            ldsm4(bbl[j], s0 + 24576u + roff);
                        }
                    } else {
                        const uint32_t krow = (uint32_t)(ks * 16 + 8 * ((lane >> 3) & 1) + (lane & 7));
                        const uint32_t rowo = krow * 256u;
#pragma unroll
                        for (int j = 0; j < 2; ++j) {
                            const uint32_t c16 = (uint32_t)((wn >> 3) + (lane >> 4) + (nh * 2 + j) * 2);
                            const uint32_t coff = ((c16 ^ (uint32_t)(lane & 7)) << 4);
                            ldsm4t(bbh[j], s0 + 16384u + rowo + coff);
                            ldsm4t(bbl[j], s0 + 24576u + rowo + coff);
                        }
                    }
#pragma unroll
                    for (int mf = 0; mf < 2; ++mf)
#pragma unroll
                        for (int j = 0; j < 2; ++j) {
                            mma16816(C[mf][nh * 4 + j * 2 + 0], aH[mf], &bbh[j][0]);
                            mma16816(C[mf][nh * 4 + j * 2 + 1], aH[mf], &bbh[j][2]);
                        }
#pragma unroll
                    for (int mf = 0; mf < 2; ++mf)
#pragma unroll
                        for (int j = 0; j < 2; ++j) {
                            mma16816(C[mf][nh * 4 + j * 2 + 0], aL[mf], &bbh[j][0]);
                            mma16816(C[mf][nh * 4 + j * 2 + 1], aL[mf], &bbh[j][2]);
                        }
#pragma unroll
                    for (int mf = 0; mf < 2; ++mf)
#pragma unroll
                        for (int j = 0; j < 2; ++j) {
                            mma16816(C[mf][nh * 4 + j * 2 + 0], aH[mf], &bbl[j][0]);
                            mma16816(C[mf][nh * 4 + j * 2 + 1], aH[mf], &bbl[j][2]);
                        }
                } else {
                    uint32_t bb[2][4];
                    if constexpr (!TRB) {
                        const uint32_t kcB = (uint32_t)(ks * 2 + ((lane >> 3) & 1));
#pragma unroll
                        for (int j = 0; j < 2; ++j) {
                            const int nf2 = nh * 2 + j;
                            const uint32_t off = 16384u + (uint32_t)(nrow + 16 * nf2) * 64u +
                                                 ((kcB ^ swzB) << 4);
                            ldsm4(bb[j], s0 + off);
                        }
                    } else {
                        const uint32_t krow = (uint32_t)(ks * 16 + 8 * ((lane >> 3) & 1) + (lane & 7));
                        const uint32_t rowo = 16384u + krow * 256u;
#pragma unroll
                        for (int j = 0; j < 2; ++j) {
                            const uint32_t c16 = (uint32_t)((wn >> 3) + (lane >> 4) + (nh * 2 + j) * 2);
                            ldsm4t(bb[j], s0 + rowo + ((c16 ^ (uint32_t)(lane & 7)) << 4));
                        }
                    }
#pragma unroll
                    for (int mf = 0; mf < 2; ++mf)
#pragma unroll
                        for (int j = 0; j < 2; ++j) {
                            mma16816(C[mf][nh * 4 + j * 2 + 0], aH[mf], &bb[j][0]);
                            mma16816(C[mf][nh * 4 + j * 2 + 1], aH[mf], &bb[j][2]);
                        }
#pragma unroll
                    for (int mf = 0; mf < 2; ++mf)
#pragma unroll
                        for (int j = 0; j < 2; ++j) {
                            mma16816(C[mf][nh * 4 + j * 2 + 0], aL[mf], &bb[j][0]);
                            mma16816(C[mf][nh * 4 + j * 2 + 1], aL[mf], &bb[j][2]);
                        }
                    if constexpr (!TRB) {
                        const uint32_t kcB = (uint32_t)(ks * 2 + ((lane >> 3) & 1));
#pragma unroll
                        for (int j = 0; j < 2; ++j) {
                            const int nf2 = nh * 2 + j;
                            const uint32_t off = 24576u + (uint32_t)(nrow + 16 * nf2) * 64u +
                                                 ((kcB ^ swzB) << 4);
                            ldsm4(bb[j], s0 + off);
                        }
                    } else {
                        const uint32_t krow = (uint32_t)(ks * 16 + 8 * ((lane >> 3) & 1) + (lane & 7));
                        const uint32_t rowo = 24576u + krow * 256u;
#pragma unroll
                        for (int j = 0; j < 2; ++j) {
                            const uint32_t c16 = (uint32_t)((wn >> 3) + (lane >> 4) + (nh * 2 + j) * 2);
                            ldsm4t(bb[j], s0 + rowo + ((c16 ^ (uint32_t)(lane & 7)) << 4));
                        }
                    }
#pragma unroll
                    for (int mf = 0; mf < 2; ++mf)
#pragma unroll
                        for (int j = 0; j < 2; ++j) {
                            mma16816(C[mf][nh * 4 + j * 2 + 0], aH[mf], &bb[j][0]);
                            mma16816(C[mf][nh * 4 + j * 2 + 1], aH[mf], &bb[j][2]);
                        }
                }
            }
        }
    }

    const int mb = m0 + wm + (lane >> 2);
    const int nbl = wn + 2 * (lane & 3);
#pragma unroll
    for (int mf = 0; mf < 2; ++mf) {
        const size_t r0 = (size_t)(mb + 16 * mf);
#pragma unroll
        for (int nf = 0; nf < 8; ++nf) {
            const int cloc = nbl + nf * 8;
            const int c = n0 + cloc;
            const float b0 = bias_s[cloc], b1 = bias_s[cloc + 1];
            const float v0 = C[mf][nf][0] * alpha + b0;
            const float v1 = C[mf][nf][1] * alpha + b1;
            const float v2 = C[mf][nf][2] * alpha + b0;
            const float v3 = C[mf][nf][3] * alpha + b1;
            if constexpr (MODE == 0) {
                *(float2*)&Cf[r0 * ldC + c]       = make_float2(v0, v1);
                *(float2*)&Cf[(r0 + 8) * ldC + c] = make_float2(v2, v3);
            } else {
                bf16 h0, l0, h1, l1, h2, l2, h3, l3;
                split2(v0, h0, l0); split2(v1, h1, l1);
                split2(v2, h2, l2); split2(v3, h3, l3);
                *(__nv_bfloat162*)&Ch[r0 * ldC + c]       = __nv_bfloat162(h0, h1);
                *(__nv_bfloat162*)&Cl[r0 * ldC + c]       = __nv_bfloat162(l0, l1);
                *(__nv_bfloat162*)&Ch[(r0 + 8) * ldC + c] = __nv_bfloat162(h2, h3);
                *(__nv_bfloat162*)&Cl[(r0 + 8) * ldC + c] = __nv_bfloat162(l2, l3);
            }
        }
    }
}

template <bool TRA, bool TRB, int MODE>
__global__ void __launch_bounds__(256, 2)
mma_gemm(const bf16* __restrict__ Ah, const bf16* __restrict__ Al, int ldA, long long sAz,
         const bf16* __restrict__ Bh, const bf16* __restrict__ Bl, int ldB, long long sBz,
         float* __restrict__ Cf, bf16* __restrict__ Ch, bf16* __restrict__ Cl,
         int ldC, long long sCz, const float* __restrict__ bias, float alpha, int K)
{
    extern __shared__ char smem[];
    const long long z = blockIdx.z;
    gemm_body<TRA, TRB, MODE, false>(
        Ah + z * sAz, Al + z * sAz, ldA, Bh + z * sBz, Bl + z * sBz, ldB,
        (MODE == 0) ? Cf + z * sCz : Cf,
        (MODE == 1) ? Ch + z * sCz : Ch,
        (MODE == 1) ? Cl + z * sCz : Cl,
        ldC, bias, alpha, K, smem);
}

// ---- fused M = Wq^T Wk and N = Wo Wv, split-K=8 each (z: 0-7 M, 8-15 N) ----
__global__ void __launch_bounds__(256, 2)
mn_gemm(const bf16* __restrict__ w1h, const bf16* __restrict__ w1l,
        const bf16* __restrict__ w2h, const bf16* __restrict__ w2l,
        const bf16* __restrict__ w3h, const bf16* __restrict__ w3l,
        const bf16* __restrict__ w4h, const bf16* __restrict__ w4l,
        float* __restrict__ part)
{
    extern __shared__ char smem[];
    const int z = blockIdx.z;
    float* Cf = part + (size_t)z * 1048576;
    if (z < 8) {
        const size_t o = (size_t)z * 384 * 1024;
        gemm_body<true, true, 0, true>(w1h + o, w1l + o, 1024, w2h + o, w2l + o, 1024,
                                       Cf, nullptr, nullptr, 1024, nullptr, 1.0f, 384, smem);
    } else {
        const int z2 = z - 8;
        const size_t oB = (size_t)z2 * 384 * 1024;
        gemm_body<false, true, 0, true>(w3h + z2 * 384, w3l + z2 * 384, 3072,
                                        w4h + oB, w4l + oB, 1024,
                                        Cf, nullptr, nullptr, 1024, nullptr, 1.0f, 384, smem);
    }
}

// ---------------------------------------------------------------------------
// prepQK: Wq/Wk splits + tvec partials. blocks: Wq [0,3072) | Wk [3072,6144)
//         | tvec [6144,6336)
// ---------------------------------------------------------------------------
__global__ void __launch_bounds__(256)
prepQK_kernel(const float* __restrict__ Wq, const float* __restrict__ Wk,
              const float* __restrict__ bq,
              bf16* __restrict__ w1h, bf16* __restrict__ w1l,
              bf16* __restrict__ w2h, bf16* __restrict__ w2l,
              float* __restrict__ tpart)
{
    __shared__ float sred[256];
    const int b = blockIdx.x;
    const int tid = threadIdx.x;

    if (b < 6144) {
        const float* src; bf16 *dh, *dl; int i0;
        if (b < 3072) { src = Wq; dh = w1h; dl = w1l; i0 = b; }
        else          { src = Wk; dh = w2h; dl = w2l; i0 = b - 3072; }
        const int i = i0 * 256 + tid;
        const float4 v = ((const float4*)src)[i];
        bf16 h0, h1, h2, h3, l0, l1, l2, l3;
        split2(v.x, h0, l0); split2(v.y, h1, l1);
        split2(v.z, h2, l2); split2(v.w, h3, l3);
        ((__nv_bfloat162*)dh)[2 * i]     = __nv_bfloat162(h0, h1);
        ((__nv_bfloat162*)dh)[2 * i + 1] = __nv_bfloat162(h2, h3);
        ((__nv_bfloat162*)dl)[2 * i]     = __nv_bfloat162(l0, l1);
        ((__nv_bfloat162*)dl)[2 * i + 1] = __nv_bfloat162(l2, l3);
    } else {
        const int t = b - 6144;           // 0..191
        const int ec = t / 8, dc = t % 8;
        const int d = dc * 128 + (tid & 127);
        const int el = tid >> 7;
        float acc = 0.0f;
#pragma unroll 8
        for (int j = 0; j < 64; ++j) {
            const int e = ec * 128 + el * 64 + j;
            acc += Wk[(size_t)e * 1024 + d] * bq[e];
        }
        sred[tid] = acc;
        __syncthreads();
        if (tid < 128) tpart[ec * 1024 + d] = sred[tid] + sred[tid + 128];
    }
}

// ---------------------------------------------------------------------------
// prepOV: Wo/Wv splits + dvec partials. blocks: Wo [0,3072) | Wv [3072,6144)
//         | dvec [6144,9216)
// ---------------------------------------------------------------------------
__global__ void __launch_bounds__(256)
prepOV_kernel(const float* __restrict__ Wo, const float* __restrict__ Wv,
              const float* __restrict__ bv,
              bf16* __restrict__ w3h, bf16* __restrict__ w3l,
              bf16* __restrict__ w4h, bf16* __restrict__ w4l,
              float* __restrict__ dpart)
{
    const int b = blockIdx.x;
    const int tid = threadIdx.x;

    if (b < 6144) {
        const float* src; bf16 *dh, *dl; int i0;
        if (b < 3072) { src = Wo; dh = w3h; dl = w3l; i0 = b; }
        else          { src = Wv; dh = w4h; dl = w4l; i0 = b - 3072; }
        const int i = i0 * 256 + tid;
        const float4 v = ((const float4*)src)[i];
        bf16 h0, h1, h2, h3, l0, l1, l2, l3;
        split2(v.x, h0, l0); split2(v.y, h1, l1);
        split2(v.z, h2, l2); split2(v.w, h3, l3);
        ((__nv_bfloat162*)dh)[2 * i]     = __nv_bfloat162(h0, h1);
        ((__nv_bfloat162*)dh)[2 * i + 1] = __nv_bfloat162(h2, h3);
        ((__nv_bfloat162*)dl)[2 * i]     = __nv_bfloat162(l0, l1);
        ((__nv_bfloat162*)dl)[2 * i + 1] = __nv_bfloat162(l2, l3);
    } else {
        const int fw = (b - 6144) * 8 + (tid >> 5);  // flat warp 0..24575
        const int row = fw / 24, ch = fw % 24;
        const int lane = tid & 31;
        const float4 a = *(const float4*)&Wo[(size_t)row * 3072 + ch * 128 + lane * 4];
        const float4 c = *(const float4*)&bv[ch * 128 + lane * 4];
        float acc = a.x * c.x + a.y * c.y + a.z * c.z + a.w * c.w;
#pragma unroll
        for (int o = 16; o > 0; o >>= 1) acc += __shfl_xor_sync(0xffffffffu, acc, o);
        if (lane == 0) dpart[ch * 1024 + row] = acc;
    }
}

// ---------------- prepX: X split only ---------------------------------------
__global__ void __launch_bounds__(256)
prepX_kernel(const float* __restrict__ x, bf16* __restrict__ xh, bf16* __restrict__ xl)
{
    const int i = blockIdx.x * 256 + threadIdx.x;
    const float4 v = ((const float4*)x)[i];
    bf16 h0, h1, h2, h3, l0, l1, l2, l3;
    split2(v.x, h0, l0); split2(v.y, h1, l1);
    split2(v.z, h2, l2); split2(v.w, h3, l3);
    ((__nv_bfloat162*)xh)[2 * i]     = __nv_bfloat162(h0, h1);
    ((__nv_bfloat162*)xh)[2 * i + 1] = __nv_bfloat162(h2, h3);
    ((__nv_bfloat162*)xl)[2 * i]     = __nv_bfloat162(l0, l1);
    ((__nv_bfloat162*)xl)[2 * i + 1] = __nv_bfloat162(l2, l3);
}

__global__ void __launch_bounds__(256)
vec_reduce(const float* __restrict__ tpart, const float* __restrict__ dpart,
           const float* __restrict__ bo, float* __restrict__ t, float* __restrict__ dv)
{
    const int i = blockIdx.x * 256 + threadIdx.x;
    if (i < 1024) {
        float a = 0.0f;
#pragma unroll
        for (int e = 0; e < 24; ++e) a += tpart[e * 1024 + i];
        t[i] = a;
    } else {
        const int j = i - 1024;
        float a = 0.0f;
#pragma unroll
        for (int e = 0; e < 24; ++e) a += dpart[e * 1024 + j];
        dv[j] = a + bo[j];
    }
}

// ---- combine one matrix (8 slabs starting at `base`) -> hi/lo split --------
__global__ void __launch_bounds__(256)
combine1(const float* __restrict__ base, bf16* __restrict__ hi, bf16* __restrict__ lo)
{
    const int i = blockIdx.x * 256 + threadIdx.x;   // float4 idx, 262144 total
    float4 x = make_float4(0.f, 0.f, 0.f, 0.f);
#pragma unroll
    for (int s2 = 0; s2 < 8; ++s2) {
        const float4 a = ((const float4*)base)[i + s2 * 262144];
        x.x += a.x; x.y += a.y; x.z += a.z; x.w += a.w;
    }
    bf16 h0, h1, h2, h3, l0, l1, l2, l3;
    split2(x.x, h0, l0); split2(x.y, h1, l1);
    split2(x.z, h2, l2); split2(x.w, h3, l3);
    ((__nv_bfloat162*)hi)[2 * i]     = __nv_bfloat162(h0, h1);
    ((__nv_bfloat162*)hi)[2 * i + 1] = __nv_bfloat162(h2, h3);
    ((__nv_bfloat162*)lo)[2 * i]     = __nv_bfloat162(l0, l1);
    ((__nv_bfloat162*)lo)[2 * i + 1] = __nv_bfloat162(l2, l3);
}

__global__ void __launch_bounds__(256)
bvec_kernel(const float* __restrict__ X, const float* __restrict__ t,
            float* __restrict__ b)
{
    const int w = (blockIdx.x * 256 + threadIdx.x) >> 5;
    const int lane = threadIdx.x & 31;
    const float* row = X + (size_t)w * 1024;
    float acc = 0.0f;
#pragma unroll
    for (int j = 0; j < 8; ++j) {
        const float4 a = *(const float4*)&row[(lane + j * 32) * 4];
        const float4 c = *(const float4*)&t[(lane + j * 32) * 4];
        acc += a.x * c.x + a.y * c.y + a.z * c.z + a.w * c.w;
    }
#pragma unroll
    for (int o = 16; o > 0; o >>= 1) acc += __shfl_xor_sync(0xffffffffu, acc, o);
    if (lane == 0) b[w] = acc;
}

__global__ void __launch_bounds__(256)
softmax_split(const float* __restrict__ S, const float* __restrict__ bvec,
              bf16* __restrict__ ph, bf16* __restrict__ pl)
{
    const long long row = blockIdx.x;
    const float* p = S + row * 2048;
    const float* bv = bvec + ((row >> 11) << 11);
    const int t = threadIdx.x;

    float4 x0 = *(const float4*)&p[t * 4];
    float4 x1 = *(const float4*)&p[1024 + t * 4];
    const float4 c0 = *(const float4*)&bv[t * 4];
    const float4 c1 = *(const float4*)&bv[1024 + t * 4];
    x0.x += 0.125f * c0.x; x0.y += 0.125f * c0.y;
    x0.z += 0.125f * c0.z; x0.w += 0.125f * c0.w;
    x1.x += 0.125f * c1.x; x1.y += 0.125f * c1.y;
    x1.z += 0.125f * c1.z; x1.w += 0.125f * c1.w;

    float m = fmaxf(fmaxf(fmaxf(x0.x, x0.y), fmaxf(x0.z, x0.w)),
                    fmaxf(fmaxf(x1.x, x1.y), fmaxf(x1.z, x1.w)));
#pragma unroll
    for (int o = 16; o > 0; o >>= 1) m = fmaxf(m, __shfl_xor_sync(0xffffffffu, m, o));
    __shared__ float red[8];
    if ((t & 31) == 0) red[t >> 5] = m;
    __syncthreads();
    m = fmaxf(fmaxf(fmaxf(red[0], red[1]), fmaxf(red[2], red[3])),
              fmaxf(fmaxf(red[4], red[5]), fmaxf(red[6], red[7])));
    __syncthreads();

    float e[8];
    e[0] = fexp(x0.x - m); e[1] = fexp(x0.y - m);
    e[2] = fexp(x0.z - m); e[3] = fexp(x0.w - m);
    e[4] = fexp(x1.x - m); e[5] = fexp(x1.y - m);
    e[6] = fexp(x1.z - m); e[7] = fexp(x1.w - m);

    float s = ((e[0] + e[1]) + (e[2] + e[3])) + ((e[4] + e[5]) + (e[6] + e[7]));
#pragma unroll
    for (int o = 16; o > 0; o >>= 1) s += __shfl_xor_sync(0xffffffffu, s, o);
    if ((t & 31) == 0) red[t >> 5] = s;
    __syncthreads();
    const float inv = 1.0f / (((red[0] + red[1]) + (red[2] + red[3])) +
                              ((red[4] + red[5]) + (red[6] + red[7])));

    bf16* hp = ph + row * 2048;
    bf16* lp = pl + row * 2048;
#pragma unroll
    for (int g = 0; g < 2; ++g) {
        bf16 hh[4], ll[4];
#pragma unroll
        for (int j = 0; j < 4; ++j) split2(e[g * 4 + j] * inv, hh[j], ll[j]);
        const int base = g * 1024 + t * 4;
        *(__nv_bfloat162*)&hp[base]     = __nv_bfloat162(hh[0], hh[1]);
        *(__nv_bfloat162*)&hp[base + 2] = __nv_bfloat162(hh[2], hh[3]);
        *(__nv_bfloat162*)&lp[base]     = __nv_bfloat162(ll[0], ll[1]);
        *(__nv_bfloat162*)&lp[base + 2] = __nv_bfloat162(ll[2], ll[3]);
    }
}

// ---------------------------------------------------------------------------
extern "C" void kernel_launch(void* const* d_in, const int* in_sizes, int n_in,
                              void* d_out, int out_size)
{
    (void)in_sizes; (void)n_in; (void)out_size;
    const float* x  = (const float*)d_in[0];
    const float* Wq = (const float*)d_in[1];
    const float* bq = (const float*)d_in[2];
    const float* Wk = (const float*)d_in[3];
    const float* bk = (const float*)d_in[4];  (void)bk;  // cancels in softmax
    const float* Wv = (const float*)d_in[5];
    const float* bv = (const float*)d_in[6];
    const float* Wo = (const float*)d_in[7];
    const float* bo = (const float*)d_in[8];
    float* out = (float*)d_out;

    bf16 *xh, *xl, *w1h, *w1l, *w2h, *w2l, *w3h, *w3l, *w4h, *w4l;
    bf16 *mh, *ml, *nh, *nl, *xmh, *xml, *ph, *pl, *c2h, *c2l;
    float *part, *tp, *dp, *s, *tv, *bvv, *dv;
    cudaGetSymbolAddress((void**)&xh, g_xh);   cudaGetSymbolAddress((void**)&xl, g_xl);
    cudaGetSymbolAddress((void**)&w1h, g_w1h); cudaGetSymbolAddress((void**)&w1l, g_w1l);
    cudaGetSymbolAddress((void**)&w2h, g_w2h); cudaGetSymbolAddress((void**)&w2l, g_w2l);
    cudaGetSymbolAddress((void**)&w3h, g_w3h); cudaGetSymbolAddress((void**)&w3l, g_w3l);
    cudaGetSymbolAddress((void**)&w4h, g_w4h); cudaGetSymbolAddress((void**)&w4l, g_w4l);
    cudaGetSymbolAddress((void**)&part, g_part);
    cudaGetSymbolAddress((void**)&tp, g_tp);   cudaGetSymbolAddress((void**)&dp, g_dp);
    cudaGetSymbolAddress((void**)&mh, g_mh);   cudaGetSymbolAddress((void**)&ml, g_ml);
    cudaGetSymbolAddress((void**)&nh, g_nh);   cudaGetSymbolAddress((void**)&nl, g_nl);
    cudaGetSymbolAddress((void**)&xmh, g_xmh); cudaGetSymbolAddress((void**)&xml, g_xml);
    cudaGetSymbolAddress((void**)&s, g_s);
    cudaGetSymbolAddress((void**)&ph, g_ph);   cudaGetSymbolAddress((void**)&pl, g_pl);
    cudaGetSymbolAddress((void**)&c2h, g_c2h); cudaGetSymbolAddress((void**)&c2l, g_c2l);
    cudaGetSymbolAddress((void**)&tv, g_tvec);
    cudaGetSymbolAddress((void**)&bvv, g_bvec);
    cudaGetSymbolAddress((void**)&dv, g_dvec);

    cudaFuncSetAttribute(mma_gemm<false, false, 0>, cudaFuncAttributeMaxDynamicSharedMemorySize, SMEM_DYN);
    cudaFuncSetAttribute(mma_gemm<false, true, 1>,  cudaFuncAttributeMaxDynamicSharedMemorySize, SMEM_DYN);
    cudaFuncSetAttribute(mn_gemm,                   cudaFuncAttributeMaxDynamicSharedMemorySize, SMEM_DYN);

    const long long QS = 2048LL * 1024, SS = 2048LL * 2048;

    cudaStream_t s0 = 0;
    cudaStream_t sB = cudaStreamPerThread;
    cudaEvent_t evRoot = g_ev[0], evQK = g_ev[1], evOV = g_ev[2],
                evMN = g_ev[3], evB = g_ev[4], evCN = g_ev[5];

    // ---- fork ---------------------------------------------------------------
    cudaEventRecord(evRoot, s0);
    cudaStreamWaitEvent(sB, evRoot, 0);

    // sB: Wo/Wv split first (mn needs it), then X split
    prepOV_kernel<<<9216, 256, 0, sB>>>(Wo, Wv, bv, w3h, w3l, w4h, w4l, dp);
    cudaEventRecord(evOV, sB);
    prepX_kernel<<<8192, 256, 0, sB>>>(x, xh, xl);

    // s0: Wq/Wk split, then the fused weight-product GEMM
    prepQK_kernel<<<6336, 256, 0, s0>>>(Wq, Wk, bq, w1h, w1l, w2h, w2l, tp);
    cudaEventRecord(evQK, s0);
    cudaStreamWaitEvent(s0, evOV, 0);
    mn_gemm<<<dim3(8, 8, 16), 256, SMEM_DYN, s0>>>(w1h, w1l, w2h, w2l,
                                                   w3h, w3l, w4h, w4l, part);
    cudaEventRecord(evMN, s0);
    combine1<<<1024, 256, 0, s0>>>(part, mh, ml);   // M half only (XM needs it)

    // sB: vectors (hidden under mn), then N-combine (hidden under XM)
    cudaStreamWaitEvent(sB, evQK, 0);
    vec_reduce<<<8, 256, 0, sB>>>(tp, dp, bo, tv, dv);
    bvec_kernel<<<1024, 256, 0, sB>>>(x, tv, bvv);
    cudaEventRecord(evB, sB);
    cudaStreamWaitEvent(sB, evMN, 0);
    combine1<<<1024, 256, 0, sB>>>(part + 8388608, nh, nl);
    cudaEventRecord(evCN, sB);

    // s0: main chain
    cudaStreamWaitEvent(s0, evB, 0);

    // XM = X * M  (B = M row-major [k][n] -> TRB)
    mma_gemm<false, true, 1><<<dim3(8, 64, 1), 256, SMEM_DYN, s0>>>(
        xh, xl, 1024, 0, mh, ml, 1024, 0,
        nullptr, xmh, xml, 1024, 0, nullptr, 1.0f, 1024);

    // scores = 0.125 * (XM) X^T per batch
    mma_gemm<false, false, 0><<<dim3(16, 16, 4), 256, SMEM_DYN, s0>>>(
        xmh, xml, 1024, QS, xh, xl, 1024, QS,
        s, nullptr, nullptr, 2048, SS, nullptr, 0.125f, 1024);

    // softmax (adds 0.125*b_m) -> split probs
    softmax_split<<<8192, 256, 0, s0>>>(s, bvv, ph, pl);

    // C2 = P X per batch (B = X [k][n] -> TRB)
    mma_gemm<false, true, 1><<<dim3(8, 16, 4), 256, SMEM_DYN, s0>>>(
        ph, pl, 2048, SS, xh, xl, 1024, QS,
        nullptr, c2h, c2l, 1024, QS, nullptr, 1.0f, 2048);

    // out = C2 N^T + d (needs N combine)
    cudaStreamWaitEvent(s0, evCN, 0);
    mma_gemm<false, false, 0><<<dim3(8, 64, 1), 256, SMEM_DYN, s0>>>(
        c2h, c2l, 1024, 0, nh, nl, 1024, 0,
        out, nullptr, nullptr, 1024, 0, dv, 1.0f, 1024);
}

// round 15
// speedup vs baseline: 1.0234x; 1.0065x over previous
#include <cuda_runtime.h>
#include <cuda_bf16.h>
#include <cstdint>

typedef __nv_bfloat16 bf16;

// ---------------- scratch (device globals; allocation is forbidden) --------
__device__ bf16 g_xh[8192 * 1024], g_xl[8192 * 1024];
__device__ bf16 g_w1h[3072 * 1024], g_w1l[3072 * 1024];  // Wq split
__device__ bf16 g_w2h[3072 * 1024], g_w2l[3072 * 1024];  // Wk split
__device__ bf16 g_w3h[3072 * 1024], g_w3l[3072 * 1024];  // Wo split
__device__ bf16 g_w4h[3072 * 1024], g_w4l[3072 * 1024];  // Wv split
__device__ float g_part[16 * 1024 * 1024];               // split-K partials (M:0-7, N:8-15)
__device__ float g_tp[24576];                            // tvec partials
__device__ float g_dp[24576];                            // dvec partials
__device__ bf16 g_mh[1024 * 1024], g_ml[1024 * 1024];    // M = Wq^T Wk
__device__ bf16 g_nh[1024 * 1024], g_nl[1024 * 1024];    // N = Wo Wv
__device__ bf16 g_xmh[8192 * 1024], g_xml[8192 * 1024];  // X*M
__device__ float g_s[8192 * 2048];                       // scores
__device__ bf16 g_ph[8192 * 2048], g_pl[8192 * 2048];    // probs
__device__ bf16 g_c2h[8192 * 1024], g_c2l[8192 * 1024];  // P*X
__device__ float g_tvec[1024];   // Wk^T bq
__device__ float g_bvec[8192];   // X * tvec
__device__ float g_dvec[1024];   // Wo bv + bo

// ---------------- events (static init; before harness mem checkpoints) ----
static cudaEvent_t g_ev[5];
namespace {
struct EvInit {
    EvInit() {
        for (int i = 0; i < 5; ++i)
            cudaEventCreateWithFlags(&g_ev[i], cudaEventDisableTiming);
    }
};
EvInit g_evinit;
}

// ---------------- helpers ---------------------------------------------------
__device__ __forceinline__ uint32_t smem_u32(const void* p) {
    uint32_t a;
    asm("{ .reg .u64 t; cvta.to.shared.u64 t, %1; cvt.u32.u64 %0, t; }"
        : "=r"(a) : "l"(p));
    return a;
}
__device__ __forceinline__ void cp16(uint32_t s, const void* g) {
    asm volatile("cp.async.cg.shared.global [%0], [%1], 16;" :: "r"(s), "l"(g));
}
__device__ __forceinline__ void cp_commit() {
    asm volatile("cp.async.commit_group;" ::: "memory");
}
__device__ __forceinline__ void cp_wait1() {
    asm volatile("cp.async.wait_group 1;" ::: "memory");
}
__device__ __forceinline__ void ldsm4(uint32_t* r, uint32_t a) {
    asm volatile("ldmatrix.sync.aligned.m8n8.x4.shared.b16 {%0,%1,%2,%3}, [%4];"
                 : "=r"(r[0]), "=r"(r[1]), "=r"(r[2]), "=r"(r[3]) : "r"(a));
}
__device__ __forceinline__ void ldsm4t(uint32_t* r, uint32_t a) {
    asm volatile("ldmatrix.sync.aligned.m8n8.x4.trans.shared.b16 {%0,%1,%2,%3}, [%4];"
                 : "=r"(r[0]), "=r"(r[1]), "=r"(r[2]), "=r"(r[3]) : "r"(a));
}
__device__ __forceinline__ void mma16816(float* d, const uint32_t* a, const uint32_t* b) {
    asm volatile("mma.sync.aligned.m16n8k16.row.col.f32.bf16.bf16.f32 "
                 "{%0,%1,%2,%3}, {%4,%5,%6,%7}, {%8,%9}, {%0,%1,%2,%3};"
                 : "+f"(d[0]), "+f"(d[1]), "+f"(d[2]), "+f"(d[3])
                 : "r"(a[0]), "r"(a[1]), "r"(a[2]), "r"(a[3]), "r"(b[0]), "r"(b[1]));
}
__device__ __forceinline__ void split2(float x, bf16& h, bf16& l) {
    h = __float2bfloat16(x);
    l = __float2bfloat16(x - __bfloat162float(h));
}
// FMA-pipe exp. rel err ~3.5e-7
__device__ __forceinline__ float fexp(float x) {
    x = fmaxf(x, -87.0f);
    const float t = x * 1.442695041f;
    const float i = rintf(t);
    const float f = t - i;
    float p = 1.54035e-4f;
    p = fmaf(p, f, 1.333356e-3f);
    p = fmaf(p, f, 9.618129e-3f);
    p = fmaf(p, f, 5.550410e-2f);
    p = fmaf(p, f, 2.402265e-1f);
    p = fmaf(p, f, 6.931472e-1f);
    p = fmaf(p, f, 1.0f);
    return __int_as_float(__float_as_int(p) + ((int)i << 23));
}

// ---------------------------------------------------------------------------
// D[m][n] = alpha * sum_k A[m][k] * B^T[n][k]  (+ bias[n])   (R11 core)
// ---------------------------------------------------------------------------
#define STG_B 32768
#define NSTG  3
#define SMEM_DYN (NSTG * STG_B)

template <bool TRA, bool TRB, int MODE, bool HOIST>
__device__ __forceinline__ void gemm_body(
    const bf16* __restrict__ Ah, const bf16* __restrict__ Al, int ldA,
    const bf16* __restrict__ Bh, const bf16* __restrict__ Bl, int ldB,
    float* __restrict__ Cf, bf16* __restrict__ Ch, bf16* __restrict__ Cl,
    int ldC, const float* __restrict__ bias, float alpha, int K, char* smem)
{
    __shared__ float bias_s[128];
    const uint32_t sb = smem_u32(smem);
    const int tid = threadIdx.x, lane = tid & 31, wid = tid >> 5;
    const int m0 = blockIdx.y * 128, n0 = blockIdx.x * 128;

    if (tid < 128) bias_s[tid] = bias ? bias[n0 + tid] : 0.0f;

    const size_t ldAs = (size_t)ldA, ldBs = (size_t)ldB;

    const int arow = tid >> 2, ac16 = tid & 3;
    const int krowL = tid >> 4, kc16 = tid & 15;
    const bf16 *pAh, *pAl;
    uint32_t sAoff;
    if constexpr (!TRA) {
        pAh = Ah + (size_t)(m0 + arow) * ldAs + ac16 * 8;
        pAl = Al + (size_t)(m0 + arow) * ldAs + ac16 * 8;
        sAoff = (uint32_t)arow * 64u + (uint32_t)((ac16 ^ ((arow >> 1) & 3)) << 4);
    } else {
        pAh = Ah + (size_t)krowL * ldAs + m0 + kc16 * 8;
        pAl = Al + (size_t)krowL * ldAs + m0 + kc16 * 8;
        sAoff = (uint32_t)krowL * 256u + (uint32_t)((kc16 ^ (krowL & 7)) << 4);
    }
    const bf16 *pBh, *pBl;
    uint32_t sBoff;
    if constexpr (!TRB) {
        pBh = Bh + (size_t)(n0 + arow) * ldBs + ac16 * 8;
        pBl = Bl + (size_t)(n0 + arow) * ldBs + ac16 * 8;
        sBoff = (uint32_t)arow * 64u + (uint32_t)((ac16 ^ ((arow >> 1) & 3)) << 4);
    } else {
        pBh = Bh + (size_t)krowL * ldBs + n0 + kc16 * 8;
        pBl = Bl + (size_t)krowL * ldBs + n0 + kc16 * 8;
        sBoff = (uint32_t)krowL * 256u + (uint32_t)((kc16 ^ (krowL & 7)) << 4);
    }

    auto load_stage = [&](int slot, int kt) {
        const uint32_t s0 = sb + (uint32_t)slot * STG_B;
        const size_t k0 = (size_t)kt * 32;
#pragma unroll
        for (int i = 0; i < 2; ++i) {
            if constexpr (!TRA) {
                cp16(s0 + i * 4096u + sAoff,         pAh + k0 + (size_t)(i * 64) * ldAs);
                cp16(s0 + 8192u + i * 4096u + sAoff, pAl + k0 + (size_t)(i * 64) * ldAs);
            } else {
                cp16(s0 + i * 4096u + sAoff,         pAh + (k0 + i * 16) * ldAs);
                cp16(s0 + 8192u + i * 4096u + sAoff, pAl + (k0 + i * 16) * ldAs);
            }
        }
#pragma unroll
        for (int i = 0; i < 2; ++i) {
            if constexpr (!TRB) {
                cp16(s0 + 16384u + i * 4096u + sBoff, pBh + k0 + (size_t)(i * 64) * ldBs);
                cp16(s0 + 24576u + i * 4096u + sBoff, pBl + k0 + (size_t)(i * 64) * ldBs);
            } else {
                cp16(s0 + 16384u + i * 4096u + sBoff, pBh + (k0 + i * 16) * ldBs);
                cp16(s0 + 24576u + i * 4096u + sBoff, pBl + (k0 + i * 16) * ldBs);
            }
        }
    };

    const int wm = (wid & 3) * 32, wn = (wid >> 2) * 64;
    const int rowAf = wm + (lane & 15);
    const uint32_t swzA = (uint32_t)((rowAf >> 1) & 3);
    const int nrow = wn + (lane & 7) + 8 * (lane >> 4);
    const uint32_t swzB = (uint32_t)((nrow >> 1) & 3);

    float C[2][8][4];
#pragma unroll
    for (int a = 0; a < 2; ++a)
#pragma unroll
        for (int b = 0; b < 8; ++b)
#pragma unroll
            for (int c = 0; c < 4; ++c) C[a][b][c] = 0.0f;

    const int nk = K >> 5;
    load_stage(0, 0); cp_commit();
    load_stage(1, 1); cp_commit();

    for (int kt = 0; kt < nk; ++kt) {
        cp_wait1();
        __syncthreads();
        if (kt + 2 < nk) load_stage((kt + 2) % NSTG, kt + 2);
        cp_commit();

        const uint32_t s0 = sb + (uint32_t)(kt % NSTG) * STG_B;
#pragma unroll
        for (int ks = 0; ks < 2; ++ks) {
            uint32_t aH[2][4], aL[2][4];
            if constexpr (!TRA) {
                const uint32_t kcA = (uint32_t)(ks * 2 + (lane >> 4));
#pragma unroll
                for (int mf = 0; mf < 2; ++mf) {
                    const uint32_t off = (uint32_t)(rowAf + 16 * mf) * 64u + ((kcA ^ swzA) << 4);
                    ldsm4(aH[mf], s0 + off);
                    ldsm4(aL[mf], s0 + 8192u + off);
                }
            } else {
                const uint32_t krow = (uint32_t)(ks * 16 + 8 * (lane >> 4) + (lane & 7));
                const uint32_t rowo = krow * 256u;
#pragma unroll
                for (int mf = 0; mf < 2; ++mf) {
                    const uint32_t c16 = (uint32_t)((wm >> 3) + 2 * mf + ((lane >> 3) & 1));
                    const uint32_t off = rowo + ((c16 ^ (uint32_t)(lane & 7)) << 4);
                    ldsm4t(aH[mf], s0 + off);
                    ldsm4t(aL[mf], s0 + 8192u + off);
                }
            }

#pragma unroll
            for (int nh = 0; nh < 2; ++nh) {
                if constexpr (HOIST) {
                    uint32_t bbh[2][4], bbl[2][4];
                    if constexpr (!TRB) {
                        const uint32_t kcB = (uint32_t)(ks * 2 + ((lane >> 3) & 1));
#pragma unroll
                        for (int j = 0; j < 2; ++j) {
                            const int nf2 = nh * 2 + j;
                            const uint32_t roff = (uint32_t)(nrow + 16 * nf2) * 64u +
                                                  ((kcB ^ swzB) << 4);
                            ldsm4(bbh[j], s0 + 16384u + roff);
                            ldsm4(bbl[j], s0 + 24576u + roff);
                        }
                    } else {
                        const uint32_t krow = (uint32_t)(ks * 16 + 8 * ((lane >> 3) & 1) + (lane & 7));
                        const uint32_t rowo = krow * 256u;
#pragma unroll
                        for (int j = 0; j < 2; ++j) {
                            const uint32_t c16 = (uint32_t)((wn >> 3) + (lane >> 4) + (nh * 2 + j) * 2);
                            const uint32_t coff = ((c16 ^ (uint32_t)(lane & 7)) << 4);
                            ldsm4t(bbh[j], s0 + 16384u + rowo + coff);
                            ldsm4t(bbl[j], s0 + 24576u + rowo + coff);
                        }
                    }
#pragma unroll
                    for (int mf = 0; mf < 2; ++mf)
#pragma unroll
                        for (int j = 0; j < 2; ++j) {
                            mma16816(C[mf][nh * 4 + j * 2 + 0], aH[mf], &bbh[j][0]);
                            mma16816(C[mf][nh * 4 + j * 2 + 1], aH[mf], &bbh[j][2]);
                        }
#pragma unroll
                    for (int mf = 0; mf < 2; ++mf)
#pragma unroll
                        for (int j = 0; j < 2; ++j) {
                            mma16816(C[mf][nh * 4 + j * 2 + 0], aL[mf], &bbh[j][0]);
                            mma16816(C[mf][nh * 4 + j * 2 + 1], aL[mf], &bbh[j][2]);
                        }
#pragma unroll
                    for (int mf = 0; mf < 2; ++mf)
#pragma unroll
                        for (int j = 0; j < 2; ++j) {
                            mma16816(C[mf][nh * 4 + j * 2 + 0], aH[mf], &bbl[j][0]);
                            mma16816(C[mf][nh * 4 + j * 2 + 1], aH[mf], &bbl[j][2]);
                        }
                } else {
                    uint32_t bb[2][4];
                    if constexpr (!TRB) {
                        const uint32_t kcB = (uint32_t)(ks * 2 + ((lane >> 3) & 1));
#pragma unroll
                        for (int j = 0; j < 2; ++j) {
                            const int nf2 = nh * 2 + j;
                            const uint32_t off = 16384u + (uint32_t)(nrow + 16 * nf2) * 64u +
                                                 ((kcB ^ swzB) << 4);
                            ldsm4(bb[j], s0 + off);
                        }
                    } else {
                        const uint32_t krow = (uint32_t)(ks * 16 + 8 * ((lane >> 3) & 1) + (lane & 7));
                        const uint32_t rowo = 16384u + krow * 256u;
#pragma unroll
                        for (int j = 0; j < 2; ++j) {
                            const uint32_t c16 = (uint32_t)((wn >> 3) + (lane >> 4) + (nh * 2 + j) * 2);
                            ldsm4t(bb[j], s0 + rowo + ((c16 ^ (uint32_t)(lane & 7)) << 4));
                        }
                    }
#pragma unroll
                    for (int mf = 0; mf < 2; ++mf)
#pragma unroll
                        for (int j = 0; j < 2; ++j) {
                            mma16816(C[mf][nh * 4 + j * 2 + 0], aH[mf], &bb[j][0]);
                            mma16816(C[mf][nh * 4 + j * 2 + 1], aH[mf], &bb[j][2]);
                        }
#pragma unroll
                    for (int mf = 0; mf < 2; ++mf)
#pragma unroll
                        for (int j = 0; j < 2; ++j) {
                            mma16816(C[mf][nh * 4 + j * 2 + 0], aL[mf], &bb[j][0]);
                            mma16816(C[mf][nh * 4 + j * 2 + 1], aL[mf], &bb[j][2]);
                        }
                    if constexpr (!TRB) {
                        const uint32_t kcB = (uint32_t)(ks * 2 + ((lane >> 3) & 1));
#pragma unroll
                        for (int j = 0; j < 2; ++j) {
                            const int nf2 = nh * 2 + j;
                            const uint32_t off = 24576u + (uint32_t)(nrow + 16 * nf2) * 64u +
                                                 ((kcB ^ swzB) << 4);
                            ldsm4(bb[j], s0 + off);
                        }
                    } else {
                        const uint32_t krow = (uint32_t)(ks * 16 + 8 * ((lane >> 3) & 1) + (lane & 7));
                        const uint32_t rowo = 24576u + krow * 256u;
#pragma unroll
                        for (int j = 0; j < 2; ++j) {
                            const uint32_t c16 = (uint32_t)((wn >> 3) + (lane >> 4) + (nh * 2 + j) * 2);
                            ldsm4t(bb[j], s0 + rowo + ((c16 ^ (uint32_t)(lane & 7)) << 4));
                        }
                    }
#pragma unroll
                    for (int mf = 0; mf < 2; ++mf)
#pragma unroll
                        for (int j = 0; j < 2; ++j) {
                            mma16816(C[mf][nh * 4 + j * 2 + 0], aH[mf], &bb[j][0]);
                            mma16816(C[mf][nh * 4 + j * 2 + 1], aH[mf], &bb[j][2]);
                        }
                }
            }
        }
    }

    const int mb = m0 + wm + (lane >> 2);
    const int nbl = wn + 2 * (lane & 3);
#pragma unroll
    for (int mf = 0; mf < 2; ++mf) {
        const size_t r0 = (size_t)(mb + 16 * mf);
#pragma unroll
        for (int nf = 0; nf < 8; ++nf) {
            const int cloc = nbl + nf * 8;
            const int c = n0 + cloc;
            const float b0 = bias_s[cloc], b1 = bias_s[cloc + 1];
            const float v0 = C[mf][nf][0] * alpha + b0;
            const float v1 = C[mf][nf][1] * alpha + b1;
            const float v2 = C[mf][nf][2] * alpha + b0;
            const float v3 = C[mf][nf][3] * alpha + b1;
            if constexpr (MODE == 0) {
                *(float2*)&Cf[r0 * ldC + c]       = make_float2(v0, v1);
                *(float2*)&Cf[(r0 + 8) * ldC + c] = make_float2(v2, v3);
            } else {
                bf16 h0, l0, h1, l1, h2, l2, h3, l3;
                split2(v0, h0, l0); split2(v1, h1, l1);
                split2(v2, h2, l2); split2(v3, h3, l3);
                *(__nv_bfloat162*)&Ch[r0 * ldC + c]       = __nv_bfloat162(h0, h1);
                *(__nv_bfloat162*)&Cl[r0 * ldC + c]       = __nv_bfloat162(l0, l1);
                *(__nv_bfloat162*)&Ch[(r0 + 8) * ldC + c] = __nv_bfloat162(h2, h3);
                *(__nv_bfloat162*)&Cl[(r0 + 8) * ldC + c] = __nv_bfloat162(l2, l3);
            }
        }
    }
}

template <bool TRA, bool TRB, int MODE>
__global__ void __launch_bounds__(256, 2)
mma_gemm(const bf16* __restrict__ Ah, const bf16* __restrict__ Al, int ldA, long long sAz,
         const bf16* __restrict__ Bh, const bf16* __restrict__ Bl, int ldB, long long sBz,
         float* __restrict__ Cf, bf16* __restrict__ Ch, bf16* __restrict__ Cl,
         int ldC, long long sCz, const float* __restrict__ bias, float alpha, int K)
{
    extern __shared__ char smem[];
    const long long z = blockIdx.z;
    gemm_body<TRA, TRB, MODE, false>(
        Ah + z * sAz, Al + z * sAz, ldA, Bh + z * sBz, Bl + z * sBz, ldB,
        (MODE == 0) ? Cf + z * sCz : Cf,
        (MODE == 1) ? Ch + z * sCz : Ch,
        (MODE == 1) ? Cl + z * sCz : Cl,
        ldC, bias, alpha, K, smem);
}

// ---- fused M = Wq^T Wk and N = Wo Wv, split-K=8 each (z: 0-7 M, 8-15 N) ----
__global__ void __launch_bounds__(256, 2)
mn_gemm(const bf16* __restrict__ w1h, const bf16* __restrict__ w1l,
        const bf16* __restrict__ w2h, const bf16* __restrict__ w2l,
        const bf16* __restrict__ w3h, const bf16* __restrict__ w3l,
        const bf16* __restrict__ w4h, const bf16* __restrict__ w4l,
        float* __restrict__ part)
{
    extern __shared__ char smem[];
    const int z = blockIdx.z;
    float* Cf = part + (size_t)z * 1048576;
    if (z < 8) {
        const size_t o = (size_t)z * 384 * 1024;
        gemm_body<true, true, 0, true>(w1h + o, w1l + o, 1024, w2h + o, w2l + o, 1024,
                                       Cf, nullptr, nullptr, 1024, nullptr, 1.0f, 384, smem);
    } else {
        const int z2 = z - 8;
        const size_t oB = (size_t)z2 * 384 * 1024;
        gemm_body<false, true, 0, true>(w3h + z2 * 384, w3l + z2 * 384, 3072,
                                        w4h + oB, w4l + oB, 1024,
                                        Cf, nullptr, nullptr, 1024, nullptr, 1.0f, 384, smem);
    }
}

// ---------------------------------------------------------------------------
// prepW: weight splits + tvec partials + dvec partials (monolithic, R12)
// blocks: Wq [0,3072) | Wk [3072,6144) | Wo [6144,9216) | Wv [9216,12288) |
//         tvec [12288,12480) | dvec [12480,15552)
// ---------------------------------------------------------------------------
__global__ void __launch_bounds__(256)
prepW_kernel(const float* __restrict__ Wq, const float* __restrict__ Wk,
             const float* __restrict__ Wv, const float* __restrict__ Wo,
             const float* __restrict__ bq, const float* __restrict__ bv,
             bf16* __restrict__ w1h, bf16* __restrict__ w1l,
             bf16* __restrict__ w2h, bf16* __restrict__ w2l,
             bf16* __restrict__ w3h, bf16* __restrict__ w3l,
             bf16* __restrict__ w4h, bf16* __restrict__ w4l,
             float* __restrict__ tpart, float* __restrict__ dpart)
{
    __shared__ float sred[256];
    const int b = blockIdx.x;
    const int tid = threadIdx.x;

    if (b < 12288) {
        const float* src; bf16 *dh, *dl; int i0;
        if (b < 3072)      { src = Wq; dh = w1h; dl = w1l; i0 = b; }
        else if (b < 6144) { src = Wk; dh = w2h; dl = w2l; i0 = b - 3072; }
        else if (b < 9216) { src = Wo; dh = w3h; dl = w3l; i0 = b - 6144; }
        else               { src = Wv; dh = w4h; dl = w4l; i0 = b - 9216; }
        const int i = i0 * 256 + tid;
        const float4 v = ((const float4*)src)[i];
        bf16 h0, h1, h2, h3, l0, l1, l2, l3;
        split2(v.x, h0, l0); split2(v.y, h1, l1);
        split2(v.z, h2, l2); split2(v.w, h3, l3);
        ((__nv_bfloat162*)dh)[2 * i]     = __nv_bfloat162(h0, h1);
        ((__nv_bfloat162*)dh)[2 * i + 1] = __nv_bfloat162(h2, h3);
        ((__nv_bfloat162*)dl)[2 * i]     = __nv_bfloat162(l0, l1);
        ((__nv_bfloat162*)dl)[2 * i + 1] = __nv_bfloat162(l2, l3);
    } else if (b < 12480) {
        const int t = b - 12288;          // 0..191
        const int ec = t / 8, dc = t % 8;
        const int d = dc * 128 + (tid & 127);
        const int el = tid >> 7;
        float acc = 0.0f;
#pragma unroll 8
        for (int j = 0; j < 64; ++j) {
            const int e = ec * 128 + el * 64 + j;
            acc += Wk[(size_t)e * 1024 + d] * bq[e];
        }
        sred[tid] = acc;
        __syncthreads();
        if (tid < 128) tpart[ec * 1024 + d] = sred[tid] + sred[tid + 128];
    } else {
        const int fw = (b - 12480) * 8 + (tid >> 5);
        const int row = fw / 24, ch = fw % 24;
        const int lane = tid & 31;
        const float4 a = *(const float4*)&Wo[(size_t)row * 3072 + ch * 128 + lane * 4];
        const float4 c = *(const float4*)&bv[ch * 128 + lane * 4];
        float acc = a.x * c.x + a.y * c.y + a.z * c.z + a.w * c.w;
#pragma unroll
        for (int o = 16; o > 0; o >>= 1) acc += __shfl_xor_sync(0xffffffffu, acc, o);
        if (lane == 0) dpart[ch * 1024 + row] = acc;
    }
}

// ---------------- prepX: X split only ---------------------------------------
__global__ void __launch_bounds__(256)
prepX_kernel(const float* __restrict__ x, bf16* __restrict__ xh, bf16* __restrict__ xl)
{
    const int i = blockIdx.x * 256 + threadIdx.x;
    const float4 v = ((const float4*)x)[i];
    bf16 h0, h1, h2, h3, l0, l1, l2, l3;
    split2(v.x, h0, l0); split2(v.y, h1, l1);
    split2(v.z, h2, l2); split2(v.w, h3, l3);
    ((__nv_bfloat162*)xh)[2 * i]     = __nv_bfloat162(h0, h1);
    ((__nv_bfloat162*)xh)[2 * i + 1] = __nv_bfloat162(h2, h3);
    ((__nv_bfloat162*)xl)[2 * i]     = __nv_bfloat162(l0, l1);
    ((__nv_bfloat162*)xl)[2 * i + 1] = __nv_bfloat162(l2, l3);
}

__global__ void __launch_bounds__(256)
vec_reduce(const float* __restrict__ tpart, const float* __restrict__ dpart,
           const float* __restrict__ bo, float* __restrict__ t, float* __restrict__ dv)
{
    const int i = blockIdx.x * 256 + threadIdx.x;
    if (i < 1024) {
        float a = 0.0f;
#pragma unroll
        for (int e = 0; e < 24; ++e) a += tpart[e * 1024 + i];
        t[i] = a;
    } else {
        const int j = i - 1024;
        float a = 0.0f;
#pragma unroll
        for (int e = 0; e < 24; ++e) a += dpart[e * 1024 + j];
        dv[j] = a + bo[j];
    }
}

// ---- combine one matrix (8 slabs starting at `base`) -> hi/lo split --------
__global__ void __launch_bounds__(256)
combine1(const float* __restrict__ base, bf16* __restrict__ hi, bf16* __restrict__ lo)
{
    const int i = blockIdx.x * 256 + threadIdx.x;   // float4 idx, 262144 total
    float4 x = make_float4(0.f, 0.f, 0.f, 0.f);
#pragma unroll
    for (int s2 = 0; s2 < 8; ++s2) {
        const float4 a = ((const float4*)base)[i + s2 * 262144];
        x.x += a.x; x.y += a.y; x.z += a.z; x.w += a.w;
    }
    bf16 h0, h1, h2, h3, l0, l1, l2, l3;
    split2(x.x, h0, l0); split2(x.y, h1, l1);
    split2(x.z, h2, l2); split2(x.w, h3, l3);
    ((__nv_bfloat162*)hi)[2 * i]     = __nv_bfloat162(h0, h1);
    ((__nv_bfloat162*)hi)[2 * i + 1] = __nv_bfloat162(h2, h3);
    ((__nv_bfloat162*)lo)[2 * i]     = __nv_bfloat162(l0, l1);
    ((__nv_bfloat162*)lo)[2 * i + 1] = __nv_bfloat162(l2, l3);
}

__global__ void __launch_bounds__(256)
bvec_kernel(const float* __restrict__ X, const float* __restrict__ t,
            float* __restrict__ b)
{
    const int w = (blockIdx.x * 256 + threadIdx.x) >> 5;
    const int lane = threadIdx.x & 31;
    const float* row = X + (size_t)w * 1024;
    float acc = 0.0f;
#pragma unroll
    for (int j = 0; j < 8; ++j) {
        const float4 a = *(const float4*)&row[(lane + j * 32) * 4];
        const float4 c = *(const float4*)&t[(lane + j * 32) * 4];
        acc += a.x * c.x + a.y * c.y + a.z * c.z + a.w * c.w;
    }
#pragma unroll
    for (int o = 16; o > 0; o >>= 1) acc += __shfl_xor_sync(0xffffffffu, acc, o);
    if (lane == 0) b[w] = acc;
}

__global__ void __launch_bounds__(256)
softmax_split(const float* __restrict__ S, const float* __restrict__ bvec,
              bf16* __restrict__ ph, bf16* __restrict__ pl)
{
    const long long row = blockIdx.x;
    const float* p = S + row * 2048;
    const float* bv = bvec + ((row >> 11) << 11);
    const int t = threadIdx.x;

    float4 x0 = *(const float4*)&p[t * 4];
    float4 x1 = *(const float4*)&p[1024 + t * 4];
    const float4 c0 = *(const float4*)&bv[t * 4];
    const float4 c1 = *(const float4*)&bv[1024 + t * 4];
    x0.x += 0.125f * c0.x; x0.y += 0.125f * c0.y;
    x0.z += 0.125f * c0.z; x0.w += 0.125f * c0.w;
    x1.x += 0.125f * c1.x; x1.y += 0.125f * c1.y;
    x1.z += 0.125f * c1.z; x1.w += 0.125f * c1.w;

    float m = fmaxf(fmaxf(fmaxf(x0.x, x0.y), fmaxf(x0.z, x0.w)),
                    fmaxf(fmaxf(x1.x, x1.y), fmaxf(x1.z, x1.w)));
#pragma unroll
    for (int o = 16; o > 0; o >>= 1) m = fmaxf(m, __shfl_xor_sync(0xffffffffu, m, o));
    __shared__ float red[8];
    if ((t & 31) == 0) red[t >> 5] = m;
    __syncthreads();
    m = fmaxf(fmaxf(fmaxf(red[0], red[1]), fmaxf(red[2], red[3])),
              fmaxf(fmaxf(red[4], red[5]), fmaxf(red[6], red[7])));
    __syncthreads();

    float e[8];
    e[0] = fexp(x0.x - m); e[1] = fexp(x0.y - m);
    e[2] = fexp(x0.z - m); e[3] = fexp(x0.w - m);
    e[4] = fexp(x1.x - m); e[5] = fexp(x1.y - m);
    e[6] = fexp(x1.z - m); e[7] = fexp(x1.w - m);

    float s = ((e[0] + e[1]) + (e[2] + e[3])) + ((e[4] + e[5]) + (e[6] + e[7]));
#pragma unroll
    for (int o = 16; o > 0; o >>= 1) s += __shfl_xor_sync(0xffffffffu, s, o);
    if ((t & 31) == 0) red[t >> 5] = s;
    __syncthreads();
    const float inv = 1.0f / (((red[0] + red[1]) + (red[2] + red[3])) +
                              ((red[4] + red[5]) + (red[6] + red[7])));

    bf16* hp = ph + row * 2048;
    bf16* lp = pl + row * 2048;
#pragma unroll
    for (int g = 0; g < 2; ++g) {
        bf16 hh[4], ll[4];
#pragma unroll
        for (int j = 0; j < 4; ++j) split2(e[g * 4 + j] * inv, hh[j], ll[j]);
        const int base = g * 1024 + t * 4;
        *(__nv_bfloat162*)&hp[base]     = __nv_bfloat162(hh[0], hh[1]);
        *(__nv_bfloat162*)&hp[base + 2] = __nv_bfloat162(hh[2], hh[3]);
        *(__nv_bfloat162*)&lp[base]     = __nv_bfloat162(ll[0], ll[1]);
        *(__nv_bfloat162*)&lp[base + 2] = __nv_bfloat162(ll[2], ll[3]);
    }
}

// ---------------------------------------------------------------------------
extern "C" void kernel_launch(void* const* d_in, const int* in_sizes, int n_in,
                              void* d_out, int out_size)
{
    (void)in_sizes; (void)n_in; (void)out_size;
    const float* x  = (const float*)d_in[0];
    const float* Wq = (const float*)d_in[1];
    const float* bq = (const float*)d_in[2];
    const float* Wk = (const float*)d_in[3];
    const float* bk = (const float*)d_in[4];  (void)bk;  // cancels in softmax
    const float* Wv = (const float*)d_in[5];
    const float* bv = (const float*)d_in[6];
    const float* Wo = (const float*)d_in[7];
    const float* bo = (const float*)d_in[8];
    float* out = (float*)d_out;

    bf16 *xh, *xl, *w1h, *w1l, *w2h, *w2l, *w3h, *w3l, *w4h, *w4l;
    bf16 *mh, *ml, *nh, *nl, *xmh, *xml, *ph, *pl, *c2h, *c2l;
    float *part, *tp, *dp, *s, *tv, *bvv, *dv;
    cudaGetSymbolAddress((void**)&xh, g_xh);   cudaGetSymbolAddress((void**)&xl, g_xl);
    cudaGetSymbolAddress((void**)&w1h, g_w1h); cudaGetSymbolAddress((void**)&w1l, g_w1l);
    cudaGetSymbolAddress((void**)&w2h, g_w2h); cudaGetSymbolAddress((void**)&w2l, g_w2l);
    cudaGetSymbolAddress((void**)&w3h, g_w3h); cudaGetSymbolAddress((void**)&w3l, g_w3l);
    cudaGetSymbolAddress((void**)&w4h, g_w4h); cudaGetSymbolAddress((void**)&w4l, g_w4l);
    cudaGetSymbolAddress((void**)&part, g_part);
    cudaGetSymbolAddress((void**)&tp, g_tp);   cudaGetSymbolAddress((void**)&dp, g_dp);
    cudaGetSymbolAddress((void**)&mh, g_mh);   cudaGetSymbolAddress((void**)&ml, g_ml);
    cudaGetSymbolAddress((void**)&nh, g_nh);   cudaGetSymbolAddress((void**)&nl, g_nl);
    cudaGetSymbolAddress((void**)&xmh, g_xmh); cudaGetSymbolAddress((void**)&xml, g_xml);
    cudaGetSymbolAddress((void**)&s, g_s);
    cudaGetSymbolAddress((void**)&ph, g_ph);   cudaGetSymbolAddress((void**)&pl, g_pl);
    cudaGetSymbolAddress((void**)&c2h, g_c2h); cudaGetSymbolAddress((void**)&c2l, g_c2l);
    cudaGetSymbolAddress((void**)&tv, g_tvec);
    cudaGetSymbolAddress((void**)&bvv, g_bvec);
    cudaGetSymbolAddress((void**)&dv, g_dvec);

    cudaFuncSetAttribute(mma_gemm<false, false, 0>, cudaFuncAttributeMaxDynamicSharedMemorySize, SMEM_DYN);
    cudaFuncSetAttribute(mma_gemm<false, true, 1>,  cudaFuncAttributeMaxDynamicSharedMemorySize, SMEM_DYN);
    cudaFuncSetAttribute(mn_gemm,                   cudaFuncAttributeMaxDynamicSharedMemorySize, SMEM_DYN);

    const long long QS = 2048LL * 1024, SS = 2048LL * 2048;

    cudaStream_t s0 = 0;                    // capture-origin stream
    cudaStream_t sB = cudaStreamPerThread;  // second stream (no creation)
    cudaEvent_t evRoot = g_ev[0], evW = g_ev[1], evB = g_ev[2],
                evMN = g_ev[3], evCN = g_ev[4];

    // ---- fork: overlap X-split + vectors with the weight-product chain -----
    cudaEventRecord(evRoot, s0);
    cudaStreamWaitEvent(sB, evRoot, 0);

    // s0: weight path (R12 structure)
    prepW_kernel<<<15552, 256, 0, s0>>>(Wq, Wk, Wv, Wo, bq, bv,
                                        w1h, w1l, w2h, w2l, w3h, w3l, w4h, w4l,
                                        tp, dp);
    cudaEventRecord(evW, s0);
    mn_gemm<<<dim3(8, 8, 16), 256, SMEM_DYN, s0>>>(w1h, w1l, w2h, w2l,
                                                   w3h, w3l, w4h, w4l, part);
    cudaEventRecord(evMN, s0);
    combine1<<<1024, 256, 0, s0>>>(part, mh, ml);   // M half only (XM needs it)

    // sB: X split + bias vectors (hidden under mn_gemm); then N-combine
    prepX_kernel<<<8192, 256, 0, sB>>>(x, xh, xl);
    cudaStreamWaitEvent(sB, evW, 0);
    vec_reduce<<<8, 256, 0, sB>>>(tp, dp, bo, tv, dv);
    bvec_kernel<<<1024, 256, 0, sB>>>(x, tv, bvv);
    cudaEventRecord(evB, sB);
    cudaStreamWaitEvent(sB, evMN, 0);
    combine1<<<1024, 256, 0, sB>>>(part + 8388608, nh, nl);  // N under XM
    cudaEventRecord(evCN, sB);

    // ---- join: serial batched main chain (R12/R11 proven sequence) ---------
    cudaStreamWaitEvent(s0, evB, 0);

    // XM = X * M  (B = M row-major [k][n] -> TRB)
    mma_gemm<false, true, 1><<<dim3(8, 64, 1), 256, SMEM_DYN, s0>>>(
        xh, xl, 1024, 0, mh, ml, 1024, 0,
        nullptr, xmh, xml, 1024, 0, nullptr, 1.0f, 1024);

    // scores = 0.125 * (XM) X^T per batch
    mma_gemm<false, false, 0><<<dim3(16, 16, 4), 256, SMEM_DYN, s0>>>(
        xmh, xml, 1024, QS, xh, xl, 1024, QS,
        s, nullptr, nullptr, 2048, SS, nullptr, 0.125f, 1024);

    // softmax (adds 0.125*b_m) -> split probs
    softmax_split<<<8192, 256, 0, s0>>>(s, bvv, ph, pl);

    // C2 = P X per batch (B = X [k][n] -> TRB)
    mma_gemm<false, true, 1><<<dim3(8, 16, 4), 256, SMEM_DYN, s0>>>(
        ph, pl, 2048, SS, xh, xl, 1024, QS,
        nullptr, c2h, c2l, 1024, QS, nullptr, 1.0f, 2048);

    // out = C2 N^T + d (needs N combine; ~600us of slack on evCN)
    cudaStreamWaitEvent(s0, evCN, 0);
    mma_gemm<false, false, 0><<<dim3(8, 64, 1), 256, SMEM_DYN, s0>>>(
        c2h, c2l, 1024, 0, nh, nl, 1024, 0,
        out, nullptr, nullptr, 1024, 0, dv, 1.0f, 1024);
}

// round 16
// speedup vs baseline: 1.0303x; 1.0067x over previous
#include <cuda_runtime.h>
#include <cuda_bf16.h>
#include <cstdint>

typedef __nv_bfloat16 bf16;

// ---------------- scratch (device globals; allocation is forbidden) --------
__device__ bf16 g_xh[8192 * 1024], g_xl[8192 * 1024];
__device__ bf16 g_w1h[3072 * 1024], g_w1l[3072 * 1024];  // Wq split
__device__ bf16 g_w2h[3072 * 1024], g_w2l[3072 * 1024];  // Wk split
__device__ bf16 g_w3h[3072 * 1024], g_w3l[3072 * 1024];  // Wo split
__device__ bf16 g_w4h[3072 * 1024], g_w4l[3072 * 1024];  // Wv split
__device__ float g_part[16 * 1024 * 1024];               // split-K partials (M:0-7, N:8-15)
__device__ float g_tp[24576];                            // tvec partials
__device__ float g_dp[24576];                            // dvec partials
__device__ bf16 g_mh[1024 * 1024], g_ml[1024 * 1024];    // M = Wq^T Wk
__device__ bf16 g_nh[1024 * 1024], g_nl[1024 * 1024];    // N = Wo Wv
__device__ bf16 g_xmh[8192 * 1024], g_xml[8192 * 1024];  // X*M
__device__ float g_s[8192 * 2048];                       // scores
__device__ bf16 g_ph[8192 * 2048], g_pl[8192 * 2048];    // probs
__device__ bf16 g_c2h[8192 * 1024], g_c2l[8192 * 1024];  // P*X
__device__ float g_tvec[1024];   // Wk^T bq
__device__ float g_bvec[8192];   // X * tvec
__device__ float g_dvec[1024];   // Wo bv + bo

// ---------------- events (static init; before harness mem checkpoints) ----
static cudaEvent_t g_ev[3];
namespace {
struct EvInit {
    EvInit() {
        for (int i = 0; i < 3; ++i)
            cudaEventCreateWithFlags(&g_ev[i], cudaEventDisableTiming);
    }
};
EvInit g_evinit;
}

// ---------------- helpers ---------------------------------------------------
__device__ __forceinline__ uint32_t smem_u32(const void* p) {
    uint32_t a;
    asm("{ .reg .u64 t; cvta.to.shared.u64 t, %1; cvt.u32.u64 %0, t; }"
        : "=r"(a) : "l"(p));
    return a;
}
__device__ __forceinline__ void cp16(uint32_t s, const void* g) {
    asm volatile("cp.async.cg.shared.global [%0], [%1], 16;" :: "r"(s), "l"(g));
}
__device__ __forceinline__ void cp_commit() {
    asm volatile("cp.async.commit_group;" ::: "memory");
}
__device__ __forceinline__ void cp_wait1() {
    asm volatile("cp.async.wait_group 1;" ::: "memory");
}
__device__ __forceinline__ void ldsm4(uint32_t* r, uint32_t a) {
    asm volatile("ldmatrix.sync.aligned.m8n8.x4.shared.b16 {%0,%1,%2,%3}, [%4];"
                 : "=r"(r[0]), "=r"(r[1]), "=r"(r[2]), "=r"(r[3]) : "r"(a));
}
__device__ __forceinline__ void ldsm4t(uint32_t* r, uint32_t a) {
    asm volatile("ldmatrix.sync.aligned.m8n8.x4.trans.shared.b16 {%0,%1,%2,%3}, [%4];"
                 : "=r"(r[0]), "=r"(r[1]), "=r"(r[2]), "=r"(r[3]) : "r"(a));
}
__device__ __forceinline__ void mma16816(float* d, const uint32_t* a, const uint32_t* b) {
    asm volatile("mma.sync.aligned.m16n8k16.row.col.f32.bf16.bf16.f32 "
                 "{%0,%1,%2,%3}, {%4,%5,%6,%7}, {%8,%9}, {%0,%1,%2,%3};"
                 : "+f"(d[0]), "+f"(d[1]), "+f"(d[2]), "+f"(d[3])
                 : "r"(a[0]), "r"(a[1]), "r"(a[2]), "r"(a[3]), "r"(b[0]), "r"(b[1]));
}
__device__ __forceinline__ void split2(float x, bf16& h, bf16& l) {
    h = __float2bfloat16(x);
    l = __float2bfloat16(x - __bfloat162float(h));
}
// FMA-pipe exp. rel err ~3.5e-7
__device__ __forceinline__ float fexp(float x) {
    x = fmaxf(x, -87.0f);
    const float t = x * 1.442695041f;
    const float i = rintf(t);
    const float f = t - i;
    float p = 1.54035e-4f;
    p = fmaf(p, f, 1.333356e-3f);
    p = fmaf(p, f, 9.618129e-3f);
    p = fmaf(p, f, 5.550410e-2f);
    p = fmaf(p, f, 2.402265e-1f);
    p = fmaf(p, f, 6.931472e-1f);
    p = fmaf(p, f, 1.0f);
    return __int_as_float(__float_as_int(p) + ((int)i << 23));
}

// ---------------------------------------------------------------------------
// D[m][n] = alpha * sum_k A[m][k] * B^T[n][k]  (+ bias[n])   (R11 core)
// ---------------------------------------------------------------------------
#define STG_B 32768
#define NSTG  3
#define SMEM_DYN (NSTG * STG_B)

template <bool TRA, bool TRB, int MODE, bool HOIST>
__device__ __forceinline__ void gemm_body(
    const bf16* __restrict__ Ah, const bf16* __restrict__ Al, int ldA,
    const bf16* __restrict__ Bh, const bf16* __restrict__ Bl, int ldB,
    float* __restrict__ Cf, bf16* __restrict__ Ch, bf16* __restrict__ Cl,
    int ldC, const float* __restrict__ bias, float alpha, int K, char* smem)
{
    __shared__ float bias_s[128];
    const uint32_t sb = smem_u32(smem);
    const int tid = threadIdx.x, lane = tid & 31, wid = tid >> 5;
    const int m0 = blockIdx.y * 128, n0 = blockIdx.x * 128;

    if (tid < 128) bias_s[tid] = bias ? bias[n0 + tid] : 0.0f;

    const size_t ldAs = (size_t)ldA, ldBs = (size_t)ldB;

    const int arow = tid >> 2, ac16 = tid & 3;
    const int krowL = tid >> 4, kc16 = tid & 15;
    const bf16 *pAh, *pAl;
    uint32_t sAoff;
    if constexpr (!TRA) {
        pAh = Ah + (size_t)(m0 + arow) * ldAs + ac16 * 8;
        pAl = Al + (size_t)(m0 + arow) * ldAs + ac16 * 8;
        sAoff = (uint32_t)arow * 64u + (uint32_t)((ac16 ^ ((arow >> 1) & 3)) << 4);
    } else {
        pAh = Ah + (size_t)krowL * ldAs + m0 + kc16 * 8;
        pAl = Al + (size_t)krowL * ldAs + m0 + kc16 * 8;
        sAoff = (uint32_t)krowL * 256u + (uint32_t)((kc16 ^ (krowL & 7)) << 4);
    }
    const bf16 *pBh, *pBl;
    uint32_t sBoff;
    if constexpr (!TRB) {
        pBh = Bh + (size_t)(n0 + arow) * ldBs + ac16 * 8;
        pBl = Bl + (size_t)(n0 + arow) * ldBs + ac16 * 8;
        sBoff = (uint32_t)arow * 64u + (uint32_t)((ac16 ^ ((arow >> 1) & 3)) << 4);
    } else {
        pBh = Bh + (size_t)krowL * ldBs + n0 + kc16 * 8;
        pBl = Bl + (size_t)krowL * ldBs + n0 + kc16 * 8;
        sBoff = (uint32_t)krowL * 256u + (uint32_t)((kc16 ^ (krowL & 7)) << 4);
    }

    auto load_stage = [&](int slot, int kt) {
        const uint32_t s0 = sb + (uint32_t)slot * STG_B;
        const size_t k0 = (size_t)kt * 32;
#pragma unroll
        for (int i = 0; i < 2; ++i) {
            if constexpr (!TRA) {
                cp16(s0 + i * 4096u + sAoff,         pAh + k0 + (size_t)(i * 64) * ldAs);
                cp16(s0 + 8192u + i * 4096u + sAoff, pAl + k0 + (size_t)(i * 64) * ldAs);
            } else {
                cp16(s0 + i * 4096u + sAoff,         pAh + (k0 + i * 16) * ldAs);
                cp16(s0 + 8192u + i * 4096u + sAoff, pAl + (k0 + i * 16) * ldAs);
            }
        }
#pragma unroll
        for (int i = 0; i < 2; ++i) {
            if constexpr (!TRB) {
                cp16(s0 + 16384u + i * 4096u + sBoff, pBh + k0 + (size_t)(i * 64) * ldBs);
                cp16(s0 + 24576u + i * 4096u + sBoff, pBl + k0 + (size_t)(i * 64) * ldBs);
            } else {
                cp16(s0 + 16384u + i * 4096u + sBoff, pBh + (k0 + i * 16) * ldBs);
                cp16(s0 + 24576u + i * 4096u + sBoff, pBl + (k0 + i * 16) * ldBs);
            }
        }
    };

    const int wm = (wid & 3) * 32, wn = (wid >> 2) * 64;
    const int rowAf = wm + (lane & 15);
    const uint32_t swzA = (uint32_t)((rowAf >> 1) & 3);
    const int nrow = wn + (lane & 7) + 8 * (lane >> 4);
    const uint32_t swzB = (uint32_t)((nrow >> 1) & 3);

    float C[2][8][4];
#pragma unroll
    for (int a = 0; a < 2; ++a)
#pragma unroll
        for (int b = 0; b < 8; ++b)
#pragma unroll
            for (int c = 0; c < 4; ++c) C[a][b][c] = 0.0f;

    const int nk = K >> 5;
    load_stage(0, 0); cp_commit();
    load_stage(1, 1); cp_commit();

    for (int kt = 0; kt < nk; ++kt) {
        cp_wait1();
        __syncthreads();
        if (kt + 2 < nk) load_stage((kt + 2) % NSTG, kt + 2);
        cp_commit();

        const uint32_t s0 = sb + (uint32_t)(kt % NSTG) * STG_B;
#pragma unroll
        for (int ks = 0; ks < 2; ++ks) {
            uint32_t aH[2][4], aL[2][4];
            if constexpr (!TRA) {
                const uint32_t kcA = (uint32_t)(ks * 2 + (lane >> 4));
#pragma unroll
                for (int mf = 0; mf < 2; ++mf) {
                    const uint32_t off = (uint32_t)(rowAf + 16 * mf) * 64u + ((kcA ^ swzA) << 4);
                    ldsm4(aH[mf], s0 + off);
                    ldsm4(aL[mf], s0 + 8192u + off);
                }
            } else {
                const uint32_t krow = (uint32_t)(ks * 16 + 8 * (lane >> 4) + (lane & 7));
                const uint32_t rowo = krow * 256u;
#pragma unroll
                for (int mf = 0; mf < 2; ++mf) {
                    const uint32_t c16 = (uint32_t)((wm >> 3) + 2 * mf + ((lane >> 3) & 1));
                    const uint32_t off = rowo + ((c16 ^ (uint32_t)(lane & 7)) << 4);
                    ldsm4t(aH[mf], s0 + off);
                    ldsm4t(aL[mf], s0 + 8192u + off);
                }
            }

#pragma unroll
            for (int nh = 0; nh < 2; ++nh) {
                if constexpr (HOIST) {
                    uint32_t bbh[2][4], bbl[2][4];
                    if constexpr (!TRB) {
                        const uint32_t kcB = (uint32_t)(ks * 2 + ((lane >> 3) & 1));
#pragma unroll
                        for (int j = 0; j < 2; ++j) {
                            const int nf2 = nh * 2 + j;
                            const uint32_t roff = (uint32_t)(nrow + 16 * nf2) * 64u +
                                                  ((kcB ^ swzB) << 4);
                            ldsm4(bbh[j], s0 + 16384u + roff);
                            ldsm4(bbl[j], s0 + 24576u + roff);
                        }
                    } else {
                        const uint32_t krow = (uint32_t)(ks * 16 + 8 * ((lane >> 3) & 1) + (lane & 7));
                        const uint32_t rowo = krow * 256u;
#pragma unroll
                        for (int j = 0; j < 2; ++j) {
                            const uint32_t c16 = (uint32_t)((wn >> 3) + (lane >> 4) + (nh * 2 + j) * 2);
                            const uint32_t coff = ((c16 ^ (uint32_t)(lane & 7)) << 4);
                            ldsm4t(bbh[j], s0 + 16384u + rowo + coff);
                            ldsm4t(bbl[j], s0 + 24576u + rowo + coff);
                        }
                    }
#pragma unroll
                    for (int mf = 0; mf < 2; ++mf)
#pragma unroll
                        for (int j = 0; j < 2; ++j) {
                            mma16816(C[mf][nh * 4 + j * 2 + 0], aH[mf], &bbh[j][0]);
                            mma16816(C[mf][nh * 4 + j * 2 + 1], aH[mf], &bbh[j][2]);
                        }
#pragma unroll
                    for (int mf = 0; mf < 2; ++mf)
#pragma unroll
                        for (int j = 0; j < 2; ++j) {
                            mma16816(C[mf][nh * 4 + j * 2 + 0], aL[mf], &bbh[j][0]);
                            mma16816(C[mf][nh * 4 + j * 2 + 1], aL[mf], &bbh[j][2]);
                        }
#pragma unroll
                    for (int mf = 0; mf < 2; ++mf)
#pragma unroll
                        for (int j = 0; j < 2; ++j) {
                            mma16816(C[mf][nh * 4 + j * 2 + 0], aH[mf], &bbl[j][0]);
                            mma16816(C[mf][nh * 4 + j * 2 + 1], aH[mf], &bbl[j][2]);
                        }
                } else {
                    uint32_t bb[2][4];
                    if constexpr (!TRB) {
                        const uint32_t kcB = (uint32_t)(ks * 2 + ((lane >> 3) & 1));
#pragma unroll
                        for (int j = 0; j < 2; ++j) {
                            const int nf2 = nh * 2 + j;
                            const uint32_t off = 16384u + (uint32_t)(nrow + 16 * nf2) * 64u +
                                                 ((kcB ^ swzB) << 4);
                            ldsm4(bb[j], s0 + off);
                        }
                    } else {
                        const uint32_t krow = (uint32_t)(ks * 16 + 8 * ((lane >> 3) & 1) + (lane & 7));
                        const uint32_t rowo = 16384u + krow * 256u;
#pragma unroll
                        for (int j = 0; j < 2; ++j) {
                            const uint32_t c16 = (uint32_t)((wn >> 3) + (lane >> 4) + (nh * 2 + j) * 2);
                            ldsm4t(bb[j], s0 + rowo + ((c16 ^ (uint32_t)(lane & 7)) << 4));
                        }
                    }
#pragma unroll
                    for (int mf = 0; mf < 2; ++mf)
#pragma unroll
                        for (int j = 0; j < 2; ++j) {
                            mma16816(C[mf][nh * 4 + j * 2 + 0], aH[mf], &bb[j][0]);
                            mma16816(C[mf][nh * 4 + j * 2 + 1], aH[mf], &bb[j][2]);
                        }
#pragma unroll
                    for (int mf = 0; mf < 2; ++mf)
#pragma unroll
                        for (int j = 0; j < 2; ++j) {
                            mma16816(C[mf][nh * 4 + j * 2 + 0], aL[mf], &bb[j][0]);
                            mma16816(C[mf][nh * 4 + j * 2 + 1], aL[mf], &bb[j][2]);
                        }
                    if constexpr (!TRB) {
                        const uint32_t kcB = (uint32_t)(ks * 2 + ((lane >> 3) & 1));
#pragma unroll
                        for (int j = 0; j < 2; ++j) {
                            const int nf2 = nh * 2 + j;
                            const uint32_t off = 24576u + (uint32_t)(nrow + 16 * nf2) * 64u +
                                                 ((kcB ^ swzB) << 4);
                            ldsm4(bb[j], s0 + off);
                        }
                    } else {
                        const uint32_t krow = (uint32_t)(ks * 16 + 8 * ((lane >> 3) & 1) + (lane & 7));
                        const uint32_t rowo = 24576u + krow * 256u;
#pragma unroll
                        for (int j = 0; j < 2; ++j) {
                            const uint32_t c16 = (uint32_t)((wn >> 3) + (lane >> 4) + (nh * 2 + j) * 2);
                            ldsm4t(bb[j], s0 + rowo + ((c16 ^ (uint32_t)(lane & 7)) << 4));
                        }
                    }
#pragma unroll
                    for (int mf = 0; mf < 2; ++mf)
#pragma unroll
                        for (int j = 0; j < 2; ++j) {
                            mma16816(C[mf][nh * 4 + j * 2 + 0], aH[mf], &bb[j][0]);
                            mma16816(C[mf][nh * 4 + j * 2 + 1], aH[mf], &bb[j][2]);
                        }
                }
            }
        }
    }

    const int mb = m0 + wm + (lane >> 2);
    const int nbl = wn + 2 * (lane & 3);
#pragma unroll
    for (int mf = 0; mf < 2; ++mf) {
        const size_t r0 = (size_t)(mb + 16 * mf);
#pragma unroll
        for (int nf = 0; nf < 8; ++nf) {
            const int cloc = nbl + nf * 8;
            const int c = n0 + cloc;
            const float b0 = bias_s[cloc], b1 = bias_s[cloc + 1];
            const float v0 = C[mf][nf][0] * alpha + b0;
            const float v1 = C[mf][nf][1] * alpha + b1;
            const float v2 = C[mf][nf][2] * alpha + b0;
            const float v3 = C[mf][nf][3] * alpha + b1;
            if constexpr (MODE == 0) {
                *(float2*)&Cf[r0 * ldC + c]       = make_float2(v0, v1);
                *(float2*)&Cf[(r0 + 8) * ldC + c] = make_float2(v2, v3);
            } else {
                bf16 h0, l0, h1, l1, h2, l2, h3, l3;
                split2(v0, h0, l0); split2(v1, h1, l1);
                split2(v2, h2, l2); split2(v3, h3, l3);
                *(__nv_bfloat162*)&Ch[r0 * ldC + c]       = __nv_bfloat162(h0, h1);
                *(__nv_bfloat162*)&Cl[r0 * ldC + c]       = __nv_bfloat162(l0, l1);
                *(__nv_bfloat162*)&Ch[(r0 + 8) * ldC + c] = __nv_bfloat162(h2, h3);
                *(__nv_bfloat162*)&Cl[(r0 + 8) * ldC + c] = __nv_bfloat162(l2, l3);
            }
        }
    }
}

template <bool TRA, bool TRB, int MODE>
__global__ void __launch_bounds__(256, 2)
mma_gemm(const bf16* __restrict__ Ah, const bf16* __restrict__ Al, int ldA, long long sAz,
         const bf16* __restrict__ Bh, const bf16* __restrict__ Bl, int ldB, long long sBz,
         float* __restrict__ Cf, bf16* __restrict__ Ch, bf16* __restrict__ Cl,
         int ldC, long long sCz, const float* __restrict__ bias, float alpha, int K)
{
    extern __shared__ char smem[];
    const long long z = blockIdx.z;
    gemm_body<TRA, TRB, MODE, false>(
        Ah + z * sAz, Al + z * sAz, ldA, Bh + z * sBz, Bl + z * sBz, ldB,
        (MODE == 0) ? Cf + z * sCz : Cf,
        (MODE == 1) ? Ch + z * sCz : Ch,
        (MODE == 1) ? Cl + z * sCz : Cl,
        ldC, bias, alpha, K, smem);
}

// ---- fused M = Wq^T Wk and N = Wo Wv, split-K=8 each (z: 0-7 M, 8-15 N) ----
__global__ void __launch_bounds__(256, 2)
mn_gemm(const bf16* __restrict__ w1h, const bf16* __restrict__ w1l,
        const bf16* __restrict__ w2h, const bf16* __restrict__ w2l,
        const bf16* __restrict__ w3h, const bf16* __restrict__ w3l,
        const bf16* __restrict__ w4h, const bf16* __restrict__ w4l,
        float* __restrict__ part)
{
    extern __shared__ char smem[];
    const int z = blockIdx.z;
    float* Cf = part + (size_t)z * 1048576;
    if (z < 8) {
        const size_t o = (size_t)z * 384 * 1024;
        gemm_body<true, true, 0, true>(w1h + o, w1l + o, 1024, w2h + o, w2l + o, 1024,
                                       Cf, nullptr, nullptr, 1024, nullptr, 1.0f, 384, smem);
    } else {
        const int z2 = z - 8;
        const size_t oB = (size_t)z2 * 384 * 1024;
        gemm_body<false, true, 0, true>(w3h + z2 * 384, w3l + z2 * 384, 3072,
                                        w4h + oB, w4l + oB, 1024,
                                        Cf, nullptr, nullptr, 1024, nullptr, 1.0f, 384, smem);
    }
}

// ---------------------------------------------------------------------------
// prepW: weight splits + tvec partials + dvec partials
// blocks: Wq [0,3072) | Wk [3072,6144) | Wo [6144,9216) | Wv [9216,12288) |
//         tvec [12288,12480) | dvec [12480,15552)
// ---------------------------------------------------------------------------
__global__ void __launch_bounds__(256)
prepW_kernel(const float* __restrict__ Wq, const float* __restrict__ Wk,
             const float* __restrict__ Wv, const float* __restrict__ Wo,
             const float* __restrict__ bq, const float* __restrict__ bv,
             bf16* __restrict__ w1h, bf16* __restrict__ w1l,
             bf16* __restrict__ w2h, bf16* __restrict__ w2l,
             bf16* __restrict__ w3h, bf16* __restrict__ w3l,
             bf16* __restrict__ w4h, bf16* __restrict__ w4l,
             float* __restrict__ tpart, float* __restrict__ dpart)
{
    __shared__ float sred[256];
    const int b = blockIdx.x;
    const int tid = threadIdx.x;

    if (b < 12288) {
        const float* src; bf16 *dh, *dl; int i0;
        if (b < 3072)      { src = Wq; dh = w1h; dl = w1l; i0 = b; }
        else if (b < 6144) { src = Wk; dh = w2h; dl = w2l; i0 = b - 3072; }
        else if (b < 9216) { src = Wo; dh = w3h; dl = w3l; i0 = b - 6144; }
        else               { src = Wv; dh = w4h; dl = w4l; i0 = b - 9216; }
        const int i = i0 * 256 + tid;
        const float4 v = ((const float4*)src)[i];
        bf16 h0, h1, h2, h3, l0, l1, l2, l3;
        split2(v.x, h0, l0); split2(v.y, h1, l1);
        split2(v.z, h2, l2); split2(v.w, h3, l3);
        ((__nv_bfloat162*)dh)[2 * i]     = __nv_bfloat162(h0, h1);
        ((__nv_bfloat162*)dh)[2 * i + 1] = __nv_bfloat162(h2, h3);
        ((__nv_bfloat162*)dl)[2 * i]     = __nv_bfloat162(l0, l1);
        ((__nv_bfloat162*)dl)[2 * i + 1] = __nv_bfloat162(l2, l3);
    } else if (b < 12480) {
        const int t = b - 12288;          // 0..191
        const int ec = t / 8, dc = t % 8;
        const int d = dc * 128 + (tid & 127);
        const int el = tid >> 7;
        float acc = 0.0f;
#pragma unroll 8
        for (int j = 0; j < 64; ++j) {
            const int e = ec * 128 + el * 64 + j;
            acc += Wk[(size_t)e * 1024 + d] * bq[e];
        }
        sred[tid] = acc;
        __syncthreads();
        if (tid < 128) tpart[ec * 1024 + d] = sred[tid] + sred[tid + 128];
    } else {
        const int fw = (b - 12480) * 8 + (tid >> 5);
        const int row = fw / 24, ch = fw % 24;
        const int lane = tid & 31;
        const float4 a = *(const float4*)&Wo[(size_t)row * 3072 + ch * 128 + lane * 4];
        const float4 c = *(const float4*)&bv[ch * 128 + lane * 4];
        float acc = a.x * c.x + a.y * c.y + a.z * c.z + a.w * c.w;
#pragma unroll
        for (int o = 16; o > 0; o >>= 1) acc += __shfl_xor_sync(0xffffffffu, acc, o);
        if (lane == 0) dpart[ch * 1024 + row] = acc;
    }
}

// ---------------- prepX: X split only ---------------------------------------
__global__ void __launch_bounds__(256)
prepX_kernel(const float* __restrict__ x, bf16* __restrict__ xh, bf16* __restrict__ xl)
{
    const int i = blockIdx.x * 256 + threadIdx.x;
    const float4 v = ((const float4*)x)[i];
    bf16 h0, h1, h2, h3, l0, l1, l2, l3;
    split2(v.x, h0, l0); split2(v.y, h1, l1);
    split2(v.z, h2, l2); split2(v.w, h3, l3);
    ((__nv_bfloat162*)xh)[2 * i]     = __nv_bfloat162(h0, h1);
    ((__nv_bfloat162*)xh)[2 * i + 1] = __nv_bfloat162(h2, h3);
    ((__nv_bfloat162*)xl)[2 * i]     = __nv_bfloat162(l0, l1);
    ((__nv_bfloat162*)xl)[2 * i + 1] = __nv_bfloat162(l2, l3);
}

__global__ void __launch_bounds__(256)
vec_reduce(const float* __restrict__ tpart, const float* __restrict__ dpart,
           const float* __restrict__ bo, float* __restrict__ t, float* __restrict__ dv)
{
    const int i = blockIdx.x * 256 + threadIdx.x;
    if (i < 1024) {
        float a = 0.0f;
#pragma unroll
        for (int e = 0; e < 24; ++e) a += tpart[e * 1024 + i];
        t[i] = a;
    } else {
        const int j = i - 1024;
        float a = 0.0f;
#pragma unroll
        for (int e = 0; e < 24; ++e) a += dpart[e * 1024 + j];
        dv[j] = a + bo[j];
    }
}

// ---- combine split-K partials (8 slabs each) for BOTH M and N --------------
__global__ void __launch_bounds__(256)
combine2(const float* __restrict__ part, bf16* __restrict__ mh, bf16* __restrict__ ml,
         bf16* __restrict__ nh, bf16* __restrict__ nl)
{
    const int bb = blockIdx.x;
    const int half = bb >> 10;
    const int i = (bb & 1023) * 256 + threadIdx.x;
    const float* p = part + (size_t)half * 8388608;
    float4 x = make_float4(0.f, 0.f, 0.f, 0.f);
#pragma unroll
    for (int s2 = 0; s2 < 8; ++s2) {
        const float4 a = ((const float4*)p)[i + s2 * 262144];
        x.x += a.x; x.y += a.y; x.z += a.z; x.w += a.w;
    }
    bf16* hi = half ? nh : mh;
    bf16* lo = half ? nl : ml;
    bf16 h0, h1, h2, h3, l0, l1, l2, l3;
    split2(x.x, h0, l0); split2(x.y, h1, l1);
    split2(x.z, h2, l2); split2(x.w, h3, l3);
    ((__nv_bfloat162*)hi)[2 * i]     = __nv_bfloat162(h0, h1);
    ((__nv_bfloat162*)hi)[2 * i + 1] = __nv_bfloat162(h2, h3);
    ((__nv_bfloat162*)lo)[2 * i]     = __nv_bfloat162(l0, l1);
    ((__nv_bfloat162*)lo)[2 * i + 1] = __nv_bfloat162(l2, l3);
}

__global__ void __launch_bounds__(256)
bvec_kernel(const float* __restrict__ X, const float* __restrict__ t,
            float* __restrict__ b)
{
    const int w = (blockIdx.x * 256 + threadIdx.x) >> 5;
    const int lane = threadIdx.x & 31;
    const float* row = X + (size_t)w * 1024;
    float acc = 0.0f;
#pragma unroll
    for (int j = 0; j < 8; ++j) {
        const float4 a = *(const float4*)&row[(lane + j * 32) * 4];
        const float4 c = *(const float4*)&t[(lane + j * 32) * 4];
        acc += a.x * c.x + a.y * c.y + a.z * c.z + a.w * c.w;
    }
#pragma unroll
    for (int o = 16; o > 0; o >>= 1) acc += __shfl_xor_sync(0xffffffffu, acc, o);
    if (lane == 0) b[w] = acc;
}

__global__ void __launch_bounds__(256)
softmax_split(const float* __restrict__ S, const float* __restrict__ bvec,
              bf16* __restrict__ ph, bf16* __restrict__ pl)
{
    const long long row = blockIdx.x;
    const float* p = S + row * 2048;
    const float* bv = bvec + ((row >> 11) << 11);
    const int t = threadIdx.x;

    float4 x0 = *(const float4*)&p[t * 4];
    float4 x1 = *(const float4*)&p[1024 + t * 4];
    const float4 c0 = *(const float4*)&bv[t * 4];
    const float4 c1 = *(const float4*)&bv[1024 + t * 4];
    x0.x += 0.125f * c0.x; x0.y += 0.125f * c0.y;
    x0.z += 0.125f * c0.z; x0.w += 0.125f * c0.w;
    x1.x += 0.125f * c1.x; x1.y += 0.125f * c1.y;
    x1.z += 0.125f * c1.z; x1.w += 0.125f * c1.w;

    float m = fmaxf(fmaxf(fmaxf(x0.x, x0.y), fmaxf(x0.z, x0.w)),
                    fmaxf(fmaxf(x1.x, x1.y), fmaxf(x1.z, x1.w)));
#pragma unroll
    for (int o = 16; o > 0; o >>= 1) m = fmaxf(m, __shfl_xor_sync(0xffffffffu, m, o));
    __shared__ float red[8];
    if ((t & 31) == 0) red[t >> 5] = m;
    __syncthreads();
    m = fmaxf(fmaxf(fmaxf(red[0], red[1]), fmaxf(red[2], red[3])),
              fmaxf(fmaxf(red[4], red[5]), fmaxf(red[6], red[7])));
    __syncthreads();

    float e[8];
    e[0] = fexp(x0.x - m); e[1] = fexp(x0.y - m);
    e[2] = fexp(x0.z - m); e[3] = fexp(x0.w - m);
    e[4] = fexp(x1.x - m); e[5] = fexp(x1.y - m);
    e[6] = fexp(x1.z - m); e[7] = fexp(x1.w - m);

    float s = ((e[0] + e[1]) + (e[2] + e[3])) + ((e[4] + e[5]) + (e[6] + e[7]));
#pragma unroll
    for (int o = 16; o > 0; o >>= 1) s += __shfl_xor_sync(0xffffffffu, s, o);
    if ((t & 31) == 0) red[t >> 5] = s;
    __syncthreads();
    const float inv = 1.0f / (((red[0] + red[1]) + (red[2] + red[3])) +
                              ((red[4] + red[5]) + (red[6] + red[7])));

    bf16* hp = ph + row * 2048;
    bf16* lp = pl + row * 2048;
#pragma unroll
    for (int g = 0; g < 2; ++g) {
        bf16 hh[4], ll[4];
#pragma unroll
        for (int j = 0; j < 4; ++j) split2(e[g * 4 + j] * inv, hh[j], ll[j]);
        const int base = g * 1024 + t * 4;
        *(__nv_bfloat162*)&hp[base]     = __nv_bfloat162(hh[0], hh[1]);
        *(__nv_bfloat162*)&hp[base + 2] = __nv_bfloat162(hh[2], hh[3]);
        *(__nv_bfloat162*)&lp[base]     = __nv_bfloat162(ll[0], ll[1]);
        *(__nv_bfloat162*)&lp[base + 2] = __nv_bfloat162(ll[2], ll[3]);
    }
}

// ---------------------------------------------------------------------------
extern "C" void kernel_launch(void* const* d_in, const int* in_sizes, int n_in,
                              void* d_out, int out_size)
{
    (void)in_sizes; (void)n_in; (void)out_size;
    const float* x  = (const float*)d_in[0];
    const float* Wq = (const float*)d_in[1];
    const float* bq = (const float*)d_in[2];
    const float* Wk = (const float*)d_in[3];
    const float* bk = (const float*)d_in[4];  (void)bk;  // cancels in softmax
    const float* Wv = (const float*)d_in[5];
    const float* bv = (const float*)d_in[6];
    const float* Wo = (const float*)d_in[7];
    const float* bo = (const float*)d_in[8];
    float* out = (float*)d_out;

    bf16 *xh, *xl, *w1h, *w1l, *w2h, *w2l, *w3h, *w3l, *w4h, *w4l;
    bf16 *mh, *ml, *nh, *nl, *xmh, *xml, *ph, *pl, *c2h, *c2l;
    float *part, *tp, *dp, *s, *tv, *bvv, *dv;
    cudaGetSymbolAddress((void**)&xh, g_xh);   cudaGetSymbolAddress((void**)&xl, g_xl);
    cudaGetSymbolAddress((void**)&w1h, g_w1h); cudaGetSymbolAddress((void**)&w1l, g_w1l);
    cudaGetSymbolAddress((void**)&w2h, g_w2h); cudaGetSymbolAddress((void**)&w2l, g_w2l);
    cudaGetSymbolAddress((void**)&w3h, g_w3h); cudaGetSymbolAddress((void**)&w3l, g_w3l);
    cudaGetSymbolAddress((void**)&w4h, g_w4h); cudaGetSymbolAddress((void**)&w4l, g_w4l);
    cudaGetSymbolAddress((void**)&part, g_part);
    cudaGetSymbolAddress((void**)&tp, g_tp);   cudaGetSymbolAddress((void**)&dp, g_dp);
    cudaGetSymbolAddress((void**)&mh, g_mh);   cudaGetSymbolAddress((void**)&ml, g_ml);
    cudaGetSymbolAddress((void**)&nh, g_nh);   cudaGetSymbolAddress((void**)&nl, g_nl);
    cudaGetSymbolAddress((void**)&xmh, g_xmh); cudaGetSymbolAddress((void**)&xml, g_xml);
    cudaGetSymbolAddress((void**)&s, g_s);
    cudaGetSymbolAddress((void**)&ph, g_ph);   cudaGetSymbolAddress((void**)&pl, g_pl);
    cudaGetSymbolAddress((void**)&c2h, g_c2h); cudaGetSymbolAddress((void**)&c2l, g_c2l);
    cudaGetSymbolAddress((void**)&tv, g_tvec);
    cudaGetSymbolAddress((void**)&bvv, g_bvec);
    cudaGetSymbolAddress((void**)&dv, g_dvec);

    cudaFuncSetAttribute(mma_gemm<false, false, 0>, cudaFuncAttributeMaxDynamicSharedMemorySize, SMEM_DYN);
    cudaFuncSetAttribute(mma_gemm<false, true, 1>,  cudaFuncAttributeMaxDynamicSharedMemorySize, SMEM_DYN);
    cudaFuncSetAttribute(mn_gemm,                   cudaFuncAttributeMaxDynamicSharedMemorySize, SMEM_DYN);

    const long long QS = 2048LL * 1024, SS = 2048LL * 2048;

    cudaStream_t s0 = 0;                    // capture-origin stream
    cudaStream_t sB = cudaStreamPerThread;  // second stream (no creation)
    cudaEvent_t evRoot = g_ev[0], evW = g_ev[1], evB = g_ev[2];

    // ---- fork: overlap X-split + vectors with the weight-product chain -----
    cudaEventRecord(evRoot, s0);
    cudaStreamWaitEvent(sB, evRoot, 0);

    // s0: weight path
    prepW_kernel<<<15552, 256, 0, s0>>>(Wq, Wk, Wv, Wo, bq, bv,
                                        w1h, w1l, w2h, w2l, w3h, w3l, w4h, w4l,
                                        tp, dp);
    cudaEventRecord(evW, s0);
    mn_gemm<<<dim3(8, 8, 16), 256, SMEM_DYN, s0>>>(w1h, w1l, w2h, w2l,
                                                   w3h, w3l, w4h, w4l, part);
    combine2<<<2048, 256, 0, s0>>>(part, mh, ml, nh, nl);

    // sB: X split + bias vectors (hidden under mn_gemm)
    prepX_kernel<<<8192, 256, 0, sB>>>(x, xh, xl);
    cudaStreamWaitEvent(sB, evW, 0);
    vec_reduce<<<8, 256, 0, sB>>>(tp, dp, bo, tv, dv);
    bvec_kernel<<<1024, 256, 0, sB>>>(x, tv, bvv);
    cudaEventRecord(evB, sB);

    // ---- join: everything below is the proven serial batched sequence ------
    cudaStreamWaitEvent(s0, evB, 0);

    // XM = X * M  (B = M row-major [k][n] -> TRB)
    mma_gemm<false, true, 1><<<dim3(8, 64, 1), 256, SMEM_DYN, s0>>>(
        xh, xl, 1024, 0, mh, ml, 1024, 0,
        nullptr, xmh, xml, 1024, 0, nullptr, 1.0f, 1024);

    // scores = 0.125 * (XM) X^T per batch
    mma_gemm<false, false, 0><<<dim3(16, 16, 4), 256, SMEM_DYN, s0>>>(
        xmh, xml, 1024, QS, xh, xl, 1024, QS,
        s, nullptr, nullptr, 2048, SS, nullptr, 0.125f, 1024);

    // softmax (adds 0.125*b_m) -> split probs
    softmax_split<<<8192, 256, 0, s0>>>(s, bvv, ph, pl);

    // C2 = P X per batch (B = X [k][n] -> TRB)
    mma_gemm<false, true, 1><<<dim3(8, 16, 4), 256, SMEM_DYN, s0>>>(
        ph, pl, 2048, SS, xh, xl, 1024, QS,
        nullptr, c2h, c2l, 1024, QS, nullptr, 1.0f, 2048);

    // out = C2 N^T + d
    mma_gemm<false, false, 0><<<dim3(8, 64, 1), 256, SMEM_DYN, s0>>>(
        c2h, c2l, 1024, 0, nh, nl, 1024, 0,
        out, nullptr, nullptr, 1024, 0, dv, 1.0f, 1024);
}

// round 17
// speedup vs baseline: 1.1771x; 1.1426x over previous
#include <cuda_runtime.h>
#include <cuda_bf16.h>
#include <cuda_fp16.h>
#include <cstdint>

typedef __nv_bfloat16 bf16;

// ---------------- scratch (device globals; allocation is forbidden) --------
__device__ bf16 g_xh[8192 * 1024], g_xl[8192 * 1024];
__device__ __half g_xf[8192 * 1024];                     // X single fp16 (C2 B operand)
__device__ bf16 g_w1h[3072 * 1024], g_w1l[3072 * 1024];  // Wq split
__device__ bf16 g_w2h[3072 * 1024], g_w2l[3072 * 1024];  // Wk split
__device__ bf16 g_w3h[3072 * 1024], g_w3l[3072 * 1024];  // Wo split
__device__ bf16 g_w4h[3072 * 1024], g_w4l[3072 * 1024];  // Wv split
__device__ float g_part[16 * 1024 * 1024];               // split-K partials (M:0-7, N:8-15)
__device__ float g_tp[24576];                            // tvec partials
__device__ float g_dp[24576];                            // dvec partials
__device__ bf16 g_mh[1024 * 1024], g_ml[1024 * 1024];    // M = Wq^T Wk (bf16 split)
__device__ __half g_nf[1024 * 1024];                     // N = Wo Wv (single fp16)
__device__ bf16 g_xmh[8192 * 1024], g_xml[8192 * 1024];  // X*M
__device__ float g_s[8192 * 2048];                       // scores
__device__ __half g_ph[8192 * 2048], g_pl[8192 * 2048];  // probs (fp16 split)
__device__ __half g_c2h[8192 * 1024], g_c2l[8192 * 1024];// P*X (fp16 split)
__device__ float g_tvec[1024];   // Wk^T bq
__device__ float g_bvec[8192];   // X * tvec
__device__ float g_dvec[1024];   // Wo bv + bo

// ---------------- events (static init; before harness mem checkpoints) ----
static cudaEvent_t g_ev[3];
namespace {
struct EvInit {
    EvInit() {
        for (int i = 0; i < 3; ++i)
            cudaEventCreateWithFlags(&g_ev[i], cudaEventDisableTiming);
    }
};
EvInit g_evinit;
}

// ---------------- helpers ---------------------------------------------------
__device__ __forceinline__ uint32_t smem_u32(const void* p) {
    uint32_t a;
    asm("{ .reg .u64 t; cvta.to.shared.u64 t, %1; cvt.u32.u64 %0, t; }"
        : "=r"(a) : "l"(p));
    return a;
}
__device__ __forceinline__ void cp16(uint32_t s, const void* g) {
    asm volatile("cp.async.cg.shared.global [%0], [%1], 16;" :: "r"(s), "l"(g));
}
__device__ __forceinline__ void cp_commit() {
    asm volatile("cp.async.commit_group;" ::: "memory");
}
__device__ __forceinline__ void cp_wait1() {
    asm volatile("cp.async.wait_group 1;" ::: "memory");
}
__device__ __forceinline__ void ldsm4(uint32_t* r, uint32_t a) {
    asm volatile("ldmatrix.sync.aligned.m8n8.x4.shared.b16 {%0,%1,%2,%3}, [%4];"
                 : "=r"(r[0]), "=r"(r[1]), "=r"(r[2]), "=r"(r[3]) : "r"(a));
}
__device__ __forceinline__ void ldsm4t(uint32_t* r, uint32_t a) {
    asm volatile("ldmatrix.sync.aligned.m8n8.x4.trans.shared.b16 {%0,%1,%2,%3}, [%4];"
                 : "=r"(r[0]), "=r"(r[1]), "=r"(r[2]), "=r"(r[3]) : "r"(a));
}
__device__ __forceinline__ void mma16816(float* d, const uint32_t* a, const uint32_t* b) {
    asm volatile("mma.sync.aligned.m16n8k16.row.col.f32.bf16.bf16.f32 "
                 "{%0,%1,%2,%3}, {%4,%5,%6,%7}, {%8,%9}, {%0,%1,%2,%3};"
                 : "+f"(d[0]), "+f"(d[1]), "+f"(d[2]), "+f"(d[3])
                 : "r"(a[0]), "r"(a[1]), "r"(a[2]), "r"(a[3]), "r"(b[0]), "r"(b[1]));
}
__device__ __forceinline__ void mma16816h(float* d, const uint32_t* a, const uint32_t* b) {
    asm volatile("mma.sync.aligned.m16n8k16.row.col.f32.f16.f16.f32 "
                 "{%0,%1,%2,%3}, {%4,%5,%6,%7}, {%8,%9}, {%0,%1,%2,%3};"
                 : "+f"(d[0]), "+f"(d[1]), "+f"(d[2]), "+f"(d[3])
                 : "r"(a[0]), "r"(a[1]), "r"(a[2]), "r"(a[3]), "r"(b[0]), "r"(b[1]));
}
template <bool F16>
__device__ __forceinline__ void mma_any(float* d, const uint32_t* a, const uint32_t* b) {
    if constexpr (F16) mma16816h(d, a, b);
    else               mma16816(d, a, b);
}
__device__ __forceinline__ void split2(float x, bf16& h, bf16& l) {
    h = __float2bfloat16(x);
    l = __float2bfloat16(x - __bfloat162float(h));
}
__device__ __forceinline__ void split2h(float x, __half& h, __half& l) {
    h = __float2half(x);
    l = __float2half(x - __half2float(h));
}
// FMA-pipe exp. rel err ~3.5e-7
__device__ __forceinline__ float fexp(float x) {
    x = fmaxf(x, -87.0f);
    const float t = x * 1.442695041f;
    const float i = rintf(t);
    const float f = t - i;
    float p = 1.54035e-4f;
    p = fmaf(p, f, 1.333356e-3f);
    p = fmaf(p, f, 9.618129e-3f);
    p = fmaf(p, f, 5.550410e-2f);
    p = fmaf(p, f, 2.402265e-1f);
    p = fmaf(p, f, 6.931472e-1f);
    p = fmaf(p, f, 1.0f);
    return __int_as_float(__float_as_int(p) + ((int)i << 23));
}

// ---------------------------------------------------------------------------
// D[m][n] = alpha * sum_k A[m][k] * B^T[n][k]  (+ bias[n])
//   F16: operands/MMA are fp16 (else bf16); MODE=1 epilogue writes same type
//   TWOTERM: B is a SINGLE array (Bh); terms Ah*B + Al*B (2 MMAs not 3)
// ---------------------------------------------------------------------------
#define STG_B 32768
#define NSTG  3
#define SMEM_DYN (NSTG * STG_B)

template <bool TRA, bool TRB, int MODE, bool HOIST, bool F16, bool TWOTERM>
__device__ __forceinline__ void gemm_body(
    const bf16* __restrict__ Ah, const bf16* __restrict__ Al, int ldA,
    const bf16* __restrict__ Bh, const bf16* __restrict__ Bl, int ldB,
    float* __restrict__ Cf, bf16* __restrict__ Ch, bf16* __restrict__ Cl,
    int ldC, const float* __restrict__ bias, float alpha, int K, char* smem)
{
    __shared__ float bias_s[128];
    const uint32_t sb = smem_u32(smem);
    const int tid = threadIdx.x, lane = tid & 31, wid = tid >> 5;
    const int m0 = blockIdx.y * 128, n0 = blockIdx.x * 128;

    if (tid < 128) bias_s[tid] = bias ? bias[n0 + tid] : 0.0f;

    const bf16* BlE = TWOTERM ? Bh : Bl;   // valid pointer even in 2-term mode
    const size_t ldAs = (size_t)ldA, ldBs = (size_t)ldB;

    const int arow = tid >> 2, ac16 = tid & 3;
    const int krowL = tid >> 4, kc16 = tid & 15;
    const bf16 *pAh, *pAl;
    uint32_t sAoff;
    if constexpr (!TRA) {
        pAh = Ah + (size_t)(m0 + arow) * ldAs + ac16 * 8;
        pAl = Al + (size_t)(m0 + arow) * ldAs + ac16 * 8;
        sAoff = (uint32_t)arow * 64u + (uint32_t)((ac16 ^ ((arow >> 1) & 3)) << 4);
    } else {
        pAh = Ah + (size_t)krowL * ldAs + m0 + kc16 * 8;
        pAl = Al + (size_t)krowL * ldAs + m0 + kc16 * 8;
        sAoff = (uint32_t)krowL * 256u + (uint32_t)((kc16 ^ (krowL & 7)) << 4);
    }
    const bf16 *pBh, *pBl;
    uint32_t sBoff;
    if constexpr (!TRB) {
        pBh = Bh  + (size_t)(n0 + arow) * ldBs + ac16 * 8;
        pBl = BlE + (size_t)(n0 + arow) * ldBs + ac16 * 8;
        sBoff = (uint32_t)arow * 64u + (uint32_t)((ac16 ^ ((arow >> 1) & 3)) << 4);
    } else {
        pBh = Bh  + (size_t)krowL * ldBs + n0 + kc16 * 8;
        pBl = BlE + (size_t)krowL * ldBs + n0 + kc16 * 8;
        sBoff = (uint32_t)krowL * 256u + (uint32_t)((kc16 ^ (krowL & 7)) << 4);
    }

    auto load_stage = [&](int slot, int kt) {
        const uint32_t s0 = sb + (uint32_t)slot * STG_B;
        const size_t k0 = (size_t)kt * 32;
#pragma unroll
        for (int i = 0; i < 2; ++i) {
            if constexpr (!TRA) {
                cp16(s0 + i * 4096u + sAoff,         pAh + k0 + (size_t)(i * 64) * ldAs);
                cp16(s0 + 8192u + i * 4096u + sAoff, pAl + k0 + (size_t)(i * 64) * ldAs);
            } else {
                cp16(s0 + i * 4096u + sAoff,         pAh + (k0 + i * 16) * ldAs);
                cp16(s0 + 8192u + i * 4096u + sAoff, pAl + (k0 + i * 16) * ldAs);
            }
        }
#pragma unroll
        for (int i = 0; i < 2; ++i) {
            if constexpr (!TRB) {
                cp16(s0 + 16384u + i * 4096u + sBoff, pBh + k0 + (size_t)(i * 64) * ldBs);
                if constexpr (!TWOTERM)
                    cp16(s0 + 24576u + i * 4096u + sBoff, pBl + k0 + (size_t)(i * 64) * ldBs);
            } else {
                cp16(s0 + 16384u + i * 4096u + sBoff, pBh + (k0 + i * 16) * ldBs);
                if constexpr (!TWOTERM)
                    cp16(s0 + 24576u + i * 4096u + sBoff, pBl + (k0 + i * 16) * ldBs);
            }
        }
    };

    const int wm = (wid & 3) * 32, wn = (wid >> 2) * 64;
    const int rowAf = wm + (lane & 15);
    const uint32_t swzA = (uint32_t)((rowAf >> 1) & 3);
    const int nrow = wn + (lane & 7) + 8 * (lane >> 4);
    const uint32_t swzB = (uint32_t)((nrow >> 1) & 3);

    float C[2][8][4];
#pragma unroll
    for (int a = 0; a < 2; ++a)
#pragma unroll
        for (int b = 0; b < 8; ++b)
#pragma unroll
            for (int c = 0; c < 4; ++c) C[a][b][c] = 0.0f;

    const int nk = K >> 5;
    load_stage(0, 0); cp_commit();
    load_stage(1, 1); cp_commit();

    for (int kt = 0; kt < nk; ++kt) {
        cp_wait1();
        __syncthreads();
        if (kt + 2 < nk) load_stage((kt + 2) % NSTG, kt + 2);
        cp_commit();

        const uint32_t s0 = sb + (uint32_t)(kt % NSTG) * STG_B;
#pragma unroll
        for (int ks = 0; ks < 2; ++ks) {
            uint32_t aH[2][4], aL[2][4];
            if constexpr (!TRA) {
                const uint32_t kcA = (uint32_t)(ks * 2 + (lane >> 4));
#pragma unroll
                for (int mf = 0; mf < 2; ++mf) {
                    const uint32_t off = (uint32_t)(rowAf + 16 * mf) * 64u + ((kcA ^ swzA) << 4);
                    ldsm4(aH[mf], s0 + off);
                    ldsm4(aL[mf], s0 + 8192u + off);
                }
            } else {
                const uint32_t krow = (uint32_t)(ks * 16 + 8 * (lane >> 4) + (lane & 7));
                const uint32_t rowo = krow * 256u;
#pragma unroll
                for (int mf = 0; mf < 2; ++mf) {
                    const uint32_t c16 = (uint32_t)((wm >> 3) + 2 * mf + ((lane >> 3) & 1));
                    const uint32_t off = rowo + ((c16 ^ (uint32_t)(lane & 7)) << 4);
                    ldsm4t(aH[mf], s0 + off);
                    ldsm4t(aL[mf], s0 + 8192u + off);
                }
            }

#pragma unroll
            for (int nh = 0; nh < 2; ++nh) {
                if constexpr (HOIST) {
                    uint32_t bbh[2][4], bbl[2][4];
                    if constexpr (!TRB) {
                        const uint32_t kcB = (uint32_t)(ks * 2 + ((lane >> 3) & 1));
#pragma unroll
                        for (int j = 0; j < 2; ++j) {
                            const int nf2 = nh * 2 + j;
                            const uint32_t roff = (uint32_t)(nrow + 16 * nf2) * 64u +
                                                  ((kcB ^ swzB) << 4);
                            ldsm4(bbh[j], s0 + 16384u + roff);
                            ldsm4(bbl[j], s0 + 24576u + roff);
                        }
                    } else {
                        const uint32_t krow = (uint32_t)(ks * 16 + 8 * ((lane >> 3) & 1) + (lane & 7));
                        const uint32_t rowo = krow * 256u;
#pragma unroll
                        for (int j = 0; j < 2; ++j) {
                            const uint32_t c16 = (uint32_t)((wn >> 3) + (lane >> 4) + (nh * 2 + j) * 2);
                            const uint32_t coff = ((c16 ^ (uint32_t)(lane & 7)) << 4);
                            ldsm4t(bbh[j], s0 + 16384u + rowo + coff);
                            ldsm4t(bbl[j], s0 + 24576u + rowo + coff);
                        }
                    }
#pragma unroll
                    for (int mf = 0; mf < 2; ++mf)
#pragma unroll
                        for (int j = 0; j < 2; ++j) {
                            mma_any<F16>(C[mf][nh * 4 + j * 2 + 0], aH[mf], &bbh[j][0]);
                            mma_any<F16>(C[mf][nh * 4 + j * 2 + 1], aH[mf], &bbh[j][2]);
                        }
#pragma unroll
                    for (int mf = 0; mf < 2; ++mf)
#pragma unroll
                        for (int j = 0; j < 2; ++j) {
                            mma_any<F16>(C[mf][nh * 4 + j * 2 + 0], aL[mf], &bbh[j][0]);
                            mma_any<F16>(C[mf][nh * 4 + j * 2 + 1], aL[mf], &bbh[j][2]);
                        }
#pragma unroll
                    for (int mf = 0; mf < 2; ++mf)
#pragma unroll
                        for (int j = 0; j < 2; ++j) {
                            mma_any<F16>(C[mf][nh * 4 + j * 2 + 0], aH[mf], &bbl[j][0]);
                            mma_any<F16>(C[mf][nh * 4 + j * 2 + 1], aH[mf], &bbl[j][2]);
                        }
                } else {
                    uint32_t bb[2][4];
                    if constexpr (!TRB) {
                        const uint32_t kcB = (uint32_t)(ks * 2 + ((lane >> 3) & 1));
#pragma unroll
                        for (int j = 0; j < 2; ++j) {
                            const int nf2 = nh * 2 + j;
                            const uint32_t off = 16384u + (uint32_t)(nrow + 16 * nf2) * 64u +
                                                 ((kcB ^ swzB) << 4);
                            ldsm4(bb[j], s0 + off);
                        }
                    } else {
                        const uint32_t krow = (uint32_t)(ks * 16 + 8 * ((lane >> 3) & 1) + (lane & 7));
                        const uint32_t rowo = 16384u + krow * 256u;
#pragma unroll
                        for (int j = 0; j < 2; ++j) {
                            const uint32_t c16 = (uint32_t)((wn >> 3) + (lane >> 4) + (nh * 2 + j) * 2);
                            ldsm4t(bb[j], s0 + rowo + ((c16 ^ (uint32_t)(lane & 7)) << 4));
                        }
                    }
#pragma unroll
                    for (int mf = 0; mf < 2; ++mf)
#pragma unroll
                        for (int j = 0; j < 2; ++j) {
                            mma_any<F16>(C[mf][nh * 4 + j * 2 + 0], aH[mf], &bb[j][0]);
                            mma_any<F16>(C[mf][nh * 4 + j * 2 + 1], aH[mf], &bb[j][2]);
                        }
#pragma unroll
                    for (int mf = 0; mf < 2; ++mf)
#pragma unroll
                        for (int j = 0; j < 2; ++j) {
                            mma_any<F16>(C[mf][nh * 4 + j * 2 + 0], aL[mf], &bb[j][0]);
                            mma_any<F16>(C[mf][nh * 4 + j * 2 + 1], aL[mf], &bb[j][2]);
                        }
                    if constexpr (!TWOTERM) {
                        if constexpr (!TRB) {
                            const uint32_t kcB = (uint32_t)(ks * 2 + ((lane >> 3) & 1));
#pragma unroll
                            for (int j = 0; j < 2; ++j) {
                                const int nf2 = nh * 2 + j;
                                const uint32_t off = 24576u + (uint32_t)(nrow + 16 * nf2) * 64u +
                                                     ((kcB ^ swzB) << 4);
                                ldsm4(bb[j], s0 + off);
                            }
                        } else {
                            const uint32_t krow = (uint32_t)(ks * 16 + 8 * ((lane >> 3) & 1) + (lane & 7));
                            const uint32_t rowo = 24576u + krow * 256u;
#pragma unroll
                            for (int j = 0; j < 2; ++j) {
                                const uint32_t c16 = (uint32_t)((wn >> 3) + (lane >> 4) + (nh * 2 + j) * 2);
                                ldsm4t(bb[j], s0 + rowo + ((c16 ^ (uint32_t)(lane & 7)) << 4));
                            }
                        }
#pragma unroll
                        for (int mf = 0; mf < 2; ++mf)
#pragma unroll
                            for (int j = 0; j < 2; ++j) {
                                mma_any<F16>(C[mf][nh * 4 + j * 2 + 0], aH[mf], &bb[j][0]);
                                mma_any<F16>(C[mf][nh * 4 + j * 2 + 1], aH[mf], &bb[j][2]);
                            }
                    }
                }
            }
        }
    }

    const int mb = m0 + wm + (lane >> 2);
    const int nbl = wn + 2 * (lane & 3);
#pragma unroll
    for (int mf = 0; mf < 2; ++mf) {
        const size_t r0 = (size_t)(mb + 16 * mf);
#pragma unroll
        for (int nf = 0; nf < 8; ++nf) {
            const int cloc = nbl + nf * 8;
            const int c = n0 + cloc;
            const float b0 = bias_s[cloc], b1 = bias_s[cloc + 1];
            const float v0 = C[mf][nf][0] * alpha + b0;
            const float v1 = C[mf][nf][1] * alpha + b1;
            const float v2 = C[mf][nf][2] * alpha + b0;
            const float v3 = C[mf][nf][3] * alpha + b1;
            if constexpr (MODE == 0) {
                *(float2*)&Cf[r0 * ldC + c]       = make_float2(v0, v1);
                *(float2*)&Cf[(r0 + 8) * ldC + c] = make_float2(v2, v3);
            } else if constexpr (F16) {
                __half* Hh = (__half*)Ch; __half* Hl = (__half*)Cl;
                __half h0, l0, h1, l1, h2, l2, h3, l3;
                split2h(v0, h0, l0); split2h(v1, h1, l1);
                split2h(v2, h2, l2); split2h(v3, h3, l3);
                *(__half2*)&Hh[r0 * ldC + c]       = __halves2half2(h0, h1);
                *(__half2*)&Hl[r0 * ldC + c]       = __halves2half2(l0, l1);
                *(__half2*)&Hh[(r0 + 8) * ldC + c] = __halves2half2(h2, h3);
                *(__half2*)&Hl[(r0 + 8) * ldC + c] = __halves2half2(l2, l3);
            } else {
                bf16 h0, l0, h1, l1, h2, l2, h3, l3;
                split2(v0, h0, l0); split2(v1, h1, l1);
                split2(v2, h2, l2); split2(v3, h3, l3);
                *(__nv_bfloat162*)&Ch[r0 * ldC + c]       = __nv_bfloat162(h0, h1);
                *(__nv_bfloat162*)&Cl[r0 * ldC + c]       = __nv_bfloat162(l0, l1);
                *(__nv_bfloat162*)&Ch[(r0 + 8) * ldC + c] = __nv_bfloat162(h2, h3);
                *(__nv_bfloat162*)&Cl[(r0 + 8) * ldC + c] = __nv_bfloat162(l2, l3);
            }
        }
    }
}

template <bool TRA, bool TRB, int MODE, bool F16, bool TWOTERM>
__global__ void __launch_bounds__(256, 2)
mma_gemm(const bf16* __restrict__ Ah, const bf16* __restrict__ Al, int ldA, long long sAz,
         const bf16* __restrict__ Bh, const bf16* __restrict__ Bl, int ldB, long long sBz,
         float* __restrict__ Cf, bf16* __restrict__ Ch, bf16* __restrict__ Cl,
         int ldC, long long sCz, const float* __restrict__ bias, float alpha, int K)
{
    extern __shared__ char smem[];
    const long long z = blockIdx.z;
    gemm_body<TRA, TRB, MODE, false, F16, TWOTERM>(
        Ah + z * sAz, Al + z * sAz, ldA, Bh + z * sBz, Bl + z * sBz, ldB,
        (MODE == 0) ? Cf + z * sCz : Cf,
        (MODE == 1) ? Ch + z * sCz : Ch,
        (MODE == 1) ? Cl + z * sCz : Cl,
        ldC, bias, alpha, K, smem);
}

// ---- fused M = Wq^T Wk and N = Wo Wv, split-K=8 each (z: 0-7 M, 8-15 N) ----
__global__ void __launch_bounds__(256, 2)
mn_gemm(const bf16* __restrict__ w1h, const bf16* __restrict__ w1l,
        const bf16* __restrict__ w2h, const bf16* __restrict__ w2l,
        const bf16* __restrict__ w3h, const bf16* __restrict__ w3l,
        const bf16* __restrict__ w4h, const bf16* __restrict__ w4l,
        float* __restrict__ part)
{
    extern __shared__ char smem[];
    const int z = blockIdx.z;
    float* Cf = part + (size_t)z * 1048576;
    if (z < 8) {
        const size_t o = (size_t)z * 384 * 1024;
        gemm_body<true, true, 0, true, false, false>(
            w1h + o, w1l + o, 1024, w2h + o, w2l + o, 1024,
            Cf, nullptr, nullptr, 1024, nullptr, 1.0f, 384, smem);
    } else {
        const int z2 = z - 8;
        const size_t oB = (size_t)z2 * 384 * 1024;
        gemm_body<false, true, 0, true, false, false>(
            w3h + z2 * 384, w3l + z2 * 384, 3072, w4h + oB, w4l + oB, 1024,
            Cf, nullptr, nullptr, 1024, nullptr, 1.0f, 384, smem);
    }
}

// ---------------------------------------------------------------------------
// prepW: weight splits + tvec partials + dvec partials
// ---------------------------------------------------------------------------
__global__ void __launch_bounds__(256)
prepW_kernel(const float* __restrict__ Wq, const float* __restrict__ Wk,
             const float* __restrict__ Wv, const float* __restrict__ Wo,
             const float* __restrict__ bq, const float* __restrict__ bv,
             bf16* __restrict__ w1h, bf16* __restrict__ w1l,
             bf16* __restrict__ w2h, bf16* __restrict__ w2l,
             bf16* __restrict__ w3h, bf16* __restrict__ w3l,
             bf16* __restrict__ w4h, bf16* __restrict__ w4l,
             float* __restrict__ tpart, float* __restrict__ dpart)
{
    __shared__ float sred[256];
    const int b = blockIdx.x;
    const int tid = threadIdx.x;

    if (b < 12288) {
        const float* src; bf16 *dh, *dl; int i0;
        if (b < 3072)      { src = Wq; dh = w1h; dl = w1l; i0 = b; }
        else if (b < 6144) { src = Wk; dh = w2h; dl = w2l; i0 = b - 3072; }
        else if (b < 9216) { src = Wo; dh = w3h; dl = w3l; i0 = b - 6144; }
        else               { src = Wv; dh = w4h; dl = w4l; i0 = b - 9216; }
        const int i = i0 * 256 + tid;
        const float4 v = ((const float4*)src)[i];
        bf16 h0, h1, h2, h3, l0, l1, l2, l3;
        split2(v.x, h0, l0); split2(v.y, h1, l1);
        split2(v.z, h2, l2); split2(v.w, h3, l3);
        ((__nv_bfloat162*)dh)[2 * i]     = __nv_bfloat162(h0, h1);
        ((__nv_bfloat162*)dh)[2 * i + 1] = __nv_bfloat162(h2, h3);
        ((__nv_bfloat162*)dl)[2 * i]     = __nv_bfloat162(l0, l1);
        ((__nv_bfloat162*)dl)[2 * i + 1] = __nv_bfloat162(l2, l3);
    } else if (b < 12480) {
        const int t = b - 12288;
        const int ec = t / 8, dc = t % 8;
        const int d = dc * 128 + (tid & 127);
        const int el = tid >> 7;
        float acc = 0.0f;
#pragma unroll 8
        for (int j = 0; j < 64; ++j) {
            const int e = ec * 128 + el * 64 + j;
            acc += Wk[(size_t)e * 1024 + d] * bq[e];
        }
        sred[tid] = acc;
        __syncthreads();
        if (tid < 128) tpart[ec * 1024 + d] = sred[tid] + sred[tid + 128];
    } else {
        const int fw = (b - 12480) * 8 + (tid >> 5);
        const int row = fw / 24, ch = fw % 24;
        const int lane = tid & 31;
        const float4 a = *(const float4*)&Wo[(size_t)row * 3072 + ch * 128 + lane * 4];
        const float4 c = *(const float4*)&bv[ch * 128 + lane * 4];
        float acc = a.x * c.x + a.y * c.y + a.z * c.z + a.w * c.w;
#pragma unroll
        for (int o = 16; o > 0; o >>= 1) acc += __shfl_xor_sync(0xffffffffu, acc, o);
        if (lane == 0) dpart[ch * 1024 + row] = acc;
    }
}

// ---------------- prepX: X split (bf16 hi/lo) + single fp16 -----------------
__global__ void __launch_bounds__(256)
prepX_kernel(const float* __restrict__ x, bf16* __restrict__ xh,
             bf16* __restrict__ xl, __half* __restrict__ xf)
{
    const int i = blockIdx.x * 256 + threadIdx.x;
    const float4 v = ((const float4*)x)[i];
    bf16 h0, h1, h2, h3, l0, l1, l2, l3;
    split2(v.x, h0, l0); split2(v.y, h1, l1);
    split2(v.z, h2, l2); split2(v.w, h3, l3);
    ((__nv_bfloat162*)xh)[2 * i]     = __nv_bfloat162(h0, h1);
    ((__nv_bfloat162*)xh)[2 * i + 1] = __nv_bfloat162(h2, h3);
    ((__nv_bfloat162*)xl)[2 * i]     = __nv_bfloat162(l0, l1);
    ((__nv_bfloat162*)xl)[2 * i + 1] = __nv_bfloat162(l2, l3);
    ((__half2*)xf)[2 * i]     = __floats2half2_rn(v.x, v.y);
    ((__half2*)xf)[2 * i + 1] = __floats2half2_rn(v.z, v.w);
}

__global__ void __launch_bounds__(256)
vec_reduce(const float* __restrict__ tpart, const float* __restrict__ dpart,
           const float* __restrict__ bo, float* __restrict__ t, float* __restrict__ dv)
{
    const int i = blockIdx.x * 256 + threadIdx.x;
    if (i < 1024) {
        float a = 0.0f;
#pragma unroll
        for (int e = 0; e < 24; ++e) a += tpart[e * 1024 + i];
        t[i] = a;
    } else {
        const int j = i - 1024;
        float a = 0.0f;
#pragma unroll
        for (int e = 0; e < 24; ++e) a += dpart[e * 1024 + j];
        dv[j] = a + bo[j];
    }
}

// ---- combine split-K partials: M -> bf16 hi/lo; N -> single fp16 -----------
__global__ void __launch_bounds__(256)
combine2(const float* __restrict__ part, bf16* __restrict__ mh, bf16* __restrict__ ml,
         __half* __restrict__ nf)
{
    const int bb = blockIdx.x;
    const int half = bb >> 10;
    const int i = (bb & 1023) * 256 + threadIdx.x;
    const float* p = part + (size_t)half * 8388608;
    float4 x = make_float4(0.f, 0.f, 0.f, 0.f);
#pragma unroll
    for (int s2 = 0; s2 < 8; ++s2) {
        const float4 a = ((const float4*)p)[i + s2 * 262144];
        x.x += a.x; x.y += a.y; x.z += a.z; x.w += a.w;
    }
    if (half == 0) {
        bf16 h0, h1, h2, h3, l0, l1, l2, l3;
        split2(x.x, h0, l0); split2(x.y, h1, l1);
        split2(x.z, h2, l2); split2(x.w, h3, l3);
        ((__nv_bfloat162*)mh)[2 * i]     = __nv_bfloat162(h0, h1);
        ((__nv_bfloat162*)mh)[2 * i + 1] = __nv_bfloat162(h2, h3);
        ((__nv_bfloat162*)ml)[2 * i]     = __nv_bfloat162(l0, l1);
        ((__nv_bfloat162*)ml)[2 * i + 1] = __nv_bfloat162(l2, l3);
    } else {
        ((__half2*)nf)[2 * i]     = __floats2half2_rn(x.x, x.y);
        ((__half2*)nf)[2 * i + 1] = __floats2half2_rn(x.z, x.w);
    }
}

__global__ void __launch_bounds__(256)
bvec_kernel(const float* __restrict__ X, const float* __restrict__ t,
            float* __restrict__ b)
{
    const int w = (blockIdx.x * 256 + threadIdx.x) >> 5;
    const int lane = threadIdx.x & 31;
    const float* row = X + (size_t)w * 1024;
    float acc = 0.0f;
#pragma unroll
    for (int j = 0; j < 8; ++j) {
        const float4 a = *(const float4*)&row[(lane + j * 32) * 4];
        const float4 c = *(const float4*)&t[(lane + j * 32) * 4];
        acc += a.x * c.x + a.y * c.y + a.z * c.z + a.w * c.w;
    }
#pragma unroll
    for (int o = 16; o > 0; o >>= 1) acc += __shfl_xor_sync(0xffffffffu, acc, o);
    if (lane == 0) b[w] = acc;
}

// ---- softmax over 2048 cols (+0.125*b_m) -> fp16 hi/lo probs ---------------
__global__ void __launch_bounds__(256)
softmax_split(const float* __restrict__ S, const float* __restrict__ bvec,
              __half* __restrict__ ph, __half* __restrict__ pl)
{
    const long long row = blockIdx.x;
    const float* p = S + row * 2048;
    const float* bv = bvec + ((row >> 11) << 11);
    const int t = threadIdx.x;

    float4 x0 = *(const float4*)&p[t * 4];
    float4 x1 = *(const float4*)&p[1024 + t * 4];
    const float4 c0 = *(const float4*)&bv[t * 4];
    const float4 c1 = *(const float4*)&bv[1024 + t * 4];
    x0.x += 0.125f * c0.x; x0.y += 0.125f * c0.y;
    x0.z += 0.125f * c0.z; x0.w += 0.125f * c0.w;
    x1.x += 0.125f * c1.x; x1.y += 0.125f * c1.y;
    x1.z += 0.125f * c1.z; x1.w += 0.125f * c1.w;

    float m = fmaxf(fmaxf(fmaxf(x0.x, x0.y), fmaxf(x0.z, x0.w)),
                    fmaxf(fmaxf(x1.x, x1.y), fmaxf(x1.z, x1.w)));
#pragma unroll
    for (int o = 16; o > 0; o >>= 1) m = fmaxf(m, __shfl_xor_sync(0xffffffffu, m, o));
    __shared__ float red[8];
    if ((t & 31) == 0) red[t >> 5] = m;
    __syncthreads();
    m = fmaxf(fmaxf(fmaxf(red[0], red[1]), fmaxf(red[2], red[3])),
              fmaxf(fmaxf(red[4], red[5]), fmaxf(red[6], red[7])));
    __syncthreads();

    float e[8];
    e[0] = fexp(x0.x - m); e[1] = fexp(x0.y - m);
    e[2] = fexp(x0.z - m); e[3] = fexp(x0.w - m);
    e[4] = fexp(x1.x - m); e[5] = fexp(x1.y - m);
    e[6] = fexp(x1.z - m); e[7] = fexp(x1.w - m);

    float s = ((e[0] + e[1]) + (e[2] + e[3])) + ((e[4] + e[5]) + (e[6] + e[7]));
#pragma unroll
    for (int o = 16; o > 0; o >>= 1) s += __shfl_xor_sync(0xffffffffu, s, o);
    if ((t & 31) == 0) red[t >> 5] = s;
    __syncthreads();
    const float inv = 1.0f / (((red[0] + red[1]) + (red[2] + red[3])) +
                              ((red[4] + red[5]) + (red[6] + red[7])));

    __half* hp = ph + row * 2048;
    __half* lp = pl + row * 2048;
#pragma unroll
    for (int g = 0; g < 2; ++g) {
        __half hh[4], ll[4];
#pragma unroll
        for (int j = 0; j < 4; ++j) split2h(e[g * 4 + j] * inv, hh[j], ll[j]);
        const int base = g * 1024 + t * 4;
        *(__half2*)&hp[base]     = __halves2half2(hh[0], hh[1]);
        *(__half2*)&hp[base + 2] = __halves2half2(hh[2], hh[3]);
        *(__half2*)&lp[base]     = __halves2half2(ll[0], ll[1]);
        *(__half2*)&lp[base + 2] = __halves2half2(ll[2], ll[3]);
    }
}

// ---------------------------------------------------------------------------
extern "C" void kernel_launch(void* const* d_in, const int* in_sizes, int n_in,
                              void* d_out, int out_size)
{
    (void)in_sizes; (void)n_in; (void)out_size;
    const float* x  = (const float*)d_in[0];
    const float* Wq = (const float*)d_in[1];
    const float* bq = (const float*)d_in[2];
    const float* Wk = (const float*)d_in[3];
    const float* bk = (const float*)d_in[4];  (void)bk;  // cancels in softmax
    const float* Wv = (const float*)d_in[5];
    const float* bv = (const float*)d_in[6];
    const float* Wo = (const float*)d_in[7];
    const float* bo = (const float*)d_in[8];
    float* out = (float*)d_out;

    bf16 *xh, *xl, *w1h, *w1l, *w2h, *w2l, *w3h, *w3l, *w4h, *w4l;
    bf16 *mh, *ml, *xmh, *xml;
    __half *xf, *nf, *ph, *pl, *c2h, *c2l;
    float *part, *tp, *dp, *s, *tv, *bvv, *dv;
    cudaGetSymbolAddress((void**)&xh, g_xh);   cudaGetSymbolAddress((void**)&xl, g_xl);
    cudaGetSymbolAddress((void**)&xf, g_xf);
    cudaGetSymbolAddress((void**)&w1h, g_w1h); cudaGetSymbolAddress((void**)&w1l, g_w1l);
    cudaGetSymbolAddress((void**)&w2h, g_w2h); cudaGetSymbolAddress((void**)&w2l, g_w2l);
    cudaGetSymbolAddress((void**)&w3h, g_w3h); cudaGetSymbolAddress((void**)&w3l, g_w3l);
    cudaGetSymbolAddress((void**)&w4h, g_w4h); cudaGetSymbolAddress((void**)&w4l, g_w4l);
    cudaGetSymbolAddress((void**)&part, g_part);
    cudaGetSymbolAddress((void**)&tp, g_tp);   cudaGetSymbolAddress((void**)&dp, g_dp);
    cudaGetSymbolAddress((void**)&mh, g_mh);   cudaGetSymbolAddress((void**)&ml, g_ml);
    cudaGetSymbolAddress((void**)&nf, g_nf);
    cudaGetSymbolAddress((void**)&xmh, g_xmh); cudaGetSymbolAddress((void**)&xml, g_xml);
    cudaGetSymbolAddress((void**)&s, g_s);
    cudaGetSymbolAddress((void**)&ph, g_ph);   cudaGetSymbolAddress((void**)&pl, g_pl);
    cudaGetSymbolAddress((void**)&c2h, g_c2h); cudaGetSymbolAddress((void**)&c2l, g_c2l);
    cudaGetSymbolAddress((void**)&tv, g_tvec);
    cudaGetSymbolAddress((void**)&bvv, g_bvec);
    cudaGetSymbolAddress((void**)&dv, g_dvec);

    cudaFuncSetAttribute(mma_gemm<false, false, 0, false, false>, cudaFuncAttributeMaxDynamicSharedMemorySize, SMEM_DYN);
    cudaFuncSetAttribute(mma_gemm<false, true, 1, false, false>,  cudaFuncAttributeMaxDynamicSharedMemorySize, SMEM_DYN);
    cudaFuncSetAttribute(mma_gemm<false, true, 1, true, true>,    cudaFuncAttributeMaxDynamicSharedMemorySize, SMEM_DYN);
    cudaFuncSetAttribute(mma_gemm<false, false, 0, true, true>,   cudaFuncAttributeMaxDynamicSharedMemorySize, SMEM_DYN);
    cudaFuncSetAttribute(mn_gemm, cudaFuncAttributeMaxDynamicSharedMemorySize, SMEM_DYN);

    const long long QS = 2048LL * 1024, SS = 2048LL * 2048;

    cudaStream_t s0 = 0;
    cudaStream_t sB = cudaStreamPerThread;
    cudaEvent_t evRoot = g_ev[0], evW = g_ev[1], evB = g_ev[2];

    // ---- fork: overlap X-split + vectors with the weight-product chain -----
    cudaEventRecord(evRoot, s0);
    cudaStreamWaitEvent(sB, evRoot, 0);

    // s0: weight path
    prepW_kernel<<<15552, 256, 0, s0>>>(Wq, Wk, Wv, Wo, bq, bv,
                                        w1h, w1l, w2h, w2l, w3h, w3l, w4h, w4l,
                                        tp, dp);
    cudaEventRecord(evW, s0);
    mn_gemm<<<dim3(8, 8, 16), 256, SMEM_DYN, s0>>>(w1h, w1l, w2h, w2l,
                                                   w3h, w3l, w4h, w4l, part);
    combine2<<<2048, 256, 0, s0>>>(part, mh, ml, nf);

    // sB: X split + bias vectors (hidden under mn_gemm)
    prepX_kernel<<<8192, 256, 0, sB>>>(x, xh, xl, xf);
    cudaStreamWaitEvent(sB, evW, 0);
    vec_reduce<<<8, 256, 0, sB>>>(tp, dp, bo, tv, dv);
    bvec_kernel<<<1024, 256, 0, sB>>>(x, tv, bvv);
    cudaEventRecord(evB, sB);

    // ---- join: serial batched main chain -----------------------------------
    cudaStreamWaitEvent(s0, evB, 0);

    // XM = X * M  (bf16 3-term)
    mma_gemm<false, true, 1, false, false><<<dim3(8, 64, 1), 256, SMEM_DYN, s0>>>(
        xh, xl, 1024, 0, mh, ml, 1024, 0,
        nullptr, xmh, xml, 1024, 0, nullptr, 1.0f, 1024);

    // scores = 0.125 * (XM) X^T per batch (bf16 3-term)
    mma_gemm<false, false, 0, false, false><<<dim3(16, 16, 4), 256, SMEM_DYN, s0>>>(
        xmh, xml, 1024, QS, xh, xl, 1024, QS,
        s, nullptr, nullptr, 2048, SS, nullptr, 0.125f, 1024);

    // softmax -> fp16 hi/lo probs
    softmax_split<<<8192, 256, 0, s0>>>(s, bvv, ph, pl);

    // C2 = P X per batch (fp16 2-term: P split, X single)
    mma_gemm<false, true, 1, true, true><<<dim3(8, 16, 4), 256, SMEM_DYN, s0>>>(
        (const bf16*)ph, (const bf16*)pl, 2048, SS,
        (const bf16*)xf, (const bf16*)xf, 1024, QS,
        nullptr, (bf16*)c2h, (bf16*)c2l, 1024, QS, nullptr, 1.0f, 2048);

    // out = C2 N^T + d (fp16 2-term: C2 split, N single)
    mma_gemm<false, false, 0, true, true><<<dim3(8, 64, 1), 256, SMEM_DYN, s0>>>(
        (const bf16*)c2h, (const bf16*)c2l, 1024, 0,
        (const bf16*)nf, (const bf16*)nf, 1024, 0,
        out, nullptr, nullptr, 1024, 0, dv, 1.0f, 1024);
}